// round 10
// baseline (speedup 1.0000x reference)
#include <cuda_runtime.h>
#include <cuda_bf16.h>
#include <cstdint>

#define B_  4
#define S_  2048
#define D_  1024
#define H_  16
#define DK_ 64
#define M_  (B_*S_)    // 8192
#define N_  (H_*DK_)   // 1024
#define KD_ D_         // 1024

// ---------------- device scratch (allocation-free rule: device globals) ----
__device__ __nv_bfloat16 g_xhi[3*M_*KD_];      // per z: Q,K,V inputs split
__device__ __nv_bfloat16 g_xlo[3*M_*KD_];
__device__ __nv_bfloat16 g_wThi[3*N_*KD_];     // per z: W transposed [n][k]
__device__ __nv_bfloat16 g_wTlo[3*N_*KD_];
__device__ __nv_bfloat16 g_qh[B_*H_*S_*DK_];   // [bh][s][64]
__device__ __nv_bfloat16 g_ql[B_*H_*S_*DK_];
__device__ __nv_bfloat16 g_kh[B_*H_*S_*DK_];
__device__ __nv_bfloat16 g_kl[B_*H_*S_*DK_];
__device__ __nv_bfloat16 g_vth[B_*H_*DK_*S_];  // V^T: [bh][d][s]
__device__ __nv_bfloat16 g_vtl[B_*H_*DK_*S_];

// ---------------- helpers ---------------------------------------------------
__device__ __forceinline__ uint32_t smem_u32(const void* p) {
    uint32_t a;
    asm("{ .reg .u64 t; cvta.to.shared.u64 t, %1; cvt.u32.u64 %0, t; }"
        : "=r"(a) : "l"(p));
    return a;
}
__device__ __forceinline__ void cp16(void* dst, const void* src) {
    asm volatile("cp.async.cg.shared.global [%0], [%1], 16;"
                 :: "r"(smem_u32(dst)), "l"(src));
}
#define CP_COMMIT() asm volatile("cp.async.commit_group;" ::: "memory")
#define CP_WAIT1()  asm volatile("cp.async.wait_group 1;" ::: "memory")
#define CP_WAIT0()  asm volatile("cp.async.wait_group 0;" ::: "memory")

__device__ __forceinline__ void mma_bf16(float* d,
                                         uint32_t a0, uint32_t a1, uint32_t a2, uint32_t a3,
                                         uint32_t b0, uint32_t b1)
{
    asm volatile(
        "mma.sync.aligned.m16n8k16.row.col.f32.bf16.bf16.f32 "
        "{%0,%1,%2,%3}, {%4,%5,%6,%7}, {%8,%9}, {%0,%1,%2,%3};"
        : "+f"(d[0]), "+f"(d[1]), "+f"(d[2]), "+f"(d[3])
        : "r"(a0), "r"(a1), "r"(a2), "r"(a3), "r"(b0), "r"(b1));
}
__device__ __forceinline__ void ldsm4(uint32_t* r, uint32_t addr) {
    asm volatile("ldmatrix.sync.aligned.m8n8.x4.shared.b16 {%0,%1,%2,%3}, [%4];"
                 : "=r"(r[0]), "=r"(r[1]), "=r"(r[2]), "=r"(r[3]) : "r"(addr));
}
__device__ __forceinline__ uint32_t pack_bf16x2(float lo, float hi) {
    uint32_t r;
    asm("cvt.rn.bf16x2.f32 %0, %1, %2;" : "=r"(r) : "f"(hi), "f"(lo));
    return r;
}
__device__ __forceinline__ float bf16_round(float x) {
    return __bfloat162float(__float2bfloat16(x));
}

// ---------------- batched fp32 -> bf16 hi/lo split ---------------------------
__global__ void split_all_kernel(const float4* __restrict__ x0,
                                 const float4* __restrict__ x1,
                                 const float4* __restrict__ x2,
                                 uint2* __restrict__ hi,
                                 uint2* __restrict__ lo, int n4)
{
    int i = blockIdx.x * blockDim.x + threadIdx.x;
    int z = blockIdx.y;
    if (i < n4) {
        const float4* x = (z == 0) ? x0 : (z == 1) ? x1 : x2;
        float4 v = x[i];
        uint2 h, l;
        h.x = pack_bf16x2(v.x, v.y);
        h.y = pack_bf16x2(v.z, v.w);
        l.x = pack_bf16x2(v.x - bf16_round(v.x), v.y - bf16_round(v.y));
        l.y = pack_bf16x2(v.z - bf16_round(v.z), v.w - bf16_round(v.w));
        hi[(size_t)z * n4 + i] = h;
        lo[(size_t)z * n4 + i] = l;
    }
}

// batched W [K][N] -> transposed hi/lo [N][K]; z = blockIdx.z
__global__ __launch_bounds__(256) void splitT_all_kernel(
    const float* __restrict__ w0, const float* __restrict__ w1,
    const float* __restrict__ w2,
    __nv_bfloat16* __restrict__ hiT, __nv_bfloat16* __restrict__ loT)
{
    __shared__ float t[32][33];
    const int tx = threadIdx.x;
    const int ty = threadIdx.y;
    const int k0 = blockIdx.y * 32;
    const int n0 = blockIdx.x * 32;
    const int z  = blockIdx.z;
    const float* w = (z == 0) ? w0 : (z == 1) ? w1 : w2;
    const size_t zo = (size_t)z * N_ * KD_;
    #pragma unroll
    for (int i = 0; i < 4; i++)
        t[ty + i * 8][tx] = w[(size_t)(k0 + ty + i * 8) * N_ + n0 + tx];
    __syncthreads();
    #pragma unroll
    for (int i = 0; i < 4; i++) {
        int n = n0 + ty + i * 8;
        int k = k0 + tx;
        float v = t[tx][ty + i * 8];
        __nv_bfloat16 h = __float2bfloat16(v);
        hiT[zo + (size_t)n * KD_ + k] = h;
        loT[zo + (size_t)n * KD_ + k] = __float2bfloat16(v - __bfloat162float(h));
    }
}

// ---------------- batched split-precision bf16 projection GEMM --------------
#define PAD      40
#define MAT_B    (128 * PAD * 2)
#define STAGE_B  (4 * MAT_B)
#define NKCH     (KD_ / 32)

__global__ __launch_bounds__(256, 2) void proj_all_kernel(
    const float* __restrict__ bq, const float* __restrict__ bk,
    const float* __restrict__ bv)
{
    extern __shared__ char psm[];

    const int tid  = threadIdx.x;
    const int wid  = tid >> 5;
    const int lane = tid & 31;
    const int wm   = wid >> 2;
    const int wn   = wid & 3;
    const int bm   = blockIdx.y * 128;
    const int bn   = blockIdx.x * 128;
    const int z    = blockIdx.z;

    const __nv_bfloat16* xhi  = g_xhi  + (size_t)z * M_ * KD_;
    const __nv_bfloat16* xlo  = g_xlo  + (size_t)z * M_ * KD_;
    const __nv_bfloat16* whiT = g_wThi + (size_t)z * N_ * KD_;
    const __nv_bfloat16* wloT = g_wTlo + (size_t)z * N_ * KD_;
    const float* bias = (z == 0) ? bq : (z == 1) ? bk : bv;
    const float scale = (z == 0) ? 0.125f : 1.0f;

    float acc[4][4][4];
    #pragma unroll
    for (int i = 0; i < 4; i++)
        #pragma unroll
        for (int j = 0; j < 4; j++)
            #pragma unroll
            for (int r = 0; r < 4; r++) acc[i][j][r] = 0.f;

    auto load_stage = [&](int c, int s) {
        const int k0 = c * 32;
        char* st = psm + s * STAGE_B;
        #pragma unroll
        for (int t = 0; t < 8; t++) {
            int idx = tid + t * 256;
            int mat = idx >> 9;
            int rr  = (idx >> 2) & 127;
            int u   = idx & 3;
            const __nv_bfloat16* src =
                (mat == 0) ? xhi : (mat == 1) ? xlo : (mat == 2) ? whiT : wloT;
            size_t off = (mat < 2)
                ? (size_t)(bm + rr) * KD_ + k0 + u * 8
                : (size_t)(bn + rr) * KD_ + k0 + u * 8;
            cp16(st + mat * MAT_B + rr * (PAD * 2) + u * 16, src + off);
        }
        CP_COMMIT();
    };

    const int fr   = lane >> 2;
    const int fc   = (lane & 3) * 2;
    const int lrow = lane & 7;
    const int lm   = lane >> 3;
    const uint32_t psm_u = smem_u32(psm);

    auto compute = [&](int s) {
        const uint32_t aHi = psm_u + s * STAGE_B;
        const uint32_t aLo = aHi + MAT_B;
        const uint32_t bHi = aHi + 2 * MAT_B;
        const uint32_t bLo = aHi + 3 * MAT_B;
        #pragma unroll
        for (int ks = 0; ks < 2; ks++) {
            const int kc = ks * 16;
            const uint32_t aoff = (uint32_t)(((lm & 1) * 8 + lrow) * (PAD * 2)
                                             + (kc + (lm >> 1) * 8) * 2);
            const uint32_t boff = (uint32_t)(((lm >> 1) * 8 + lrow) * (PAD * 2)
                                             + (kc + (lm & 1) * 8) * 2);
            uint32_t af[4][4], al[4][4], bh[8], bl[8];
            #pragma unroll
            for (int i = 0; i < 4; i++) {
                uint32_t ra = (uint32_t)((wm * 64 + i * 16) * (PAD * 2));
                ldsm4(af[i], aHi + ra + aoff);
                ldsm4(al[i], aLo + ra + aoff);
            }
            #pragma unroll
            for (int jb = 0; jb < 2; jb++) {
                uint32_t rb = (uint32_t)((wn * 32 + jb * 16) * (PAD * 2));
                ldsm4(&bh[jb * 4], bHi + rb + boff);
                ldsm4(&bl[jb * 4], bLo + rb + boff);
            }
            #pragma unroll
            for (int i = 0; i < 4; i++)
                #pragma unroll
                for (int j = 0; j < 4; j++) {
                    mma_bf16(acc[i][j], af[i][0], af[i][1], af[i][2], af[i][3],
                             bh[j * 2], bh[j * 2 + 1]);
                    mma_bf16(acc[i][j], af[i][0], af[i][1], af[i][2], af[i][3],
                             bl[j * 2], bl[j * 2 + 1]);
                    mma_bf16(acc[i][j], al[i][0], al[i][1], al[i][2], al[i][3],
                             bh[j * 2], bh[j * 2 + 1]);
                }
        }
    };

    load_stage(0, 0);
    for (int c = 0; c < NKCH; c++) {
        const int s = c & 1;
        if (c + 1 < NKCH) load_stage(c + 1, s ^ 1);
        if (c + 1 < NKCH) { CP_WAIT1(); } else { CP_WAIT0(); }
        __syncthreads();
        compute(s);
        __syncthreads();
    }

    // epilogue: bias+scale, split hi/lo, write (V transposed when z==2)
    #pragma unroll
    for (int i = 0; i < 4; i++) {
        #pragma unroll
        for (int rr = 0; rr < 2; rr++) {
            int m = bm + wm * 64 + i * 16 + fr + rr * 8;
            int b = m >> 11;
            int sdx = m & (S_ - 1);
            #pragma unroll
            for (int j = 0; j < 4; j++) {
                int n0 = bn + wn * 32 + j * 8 + fc;
                int h  = n0 >> 6;
                int d  = n0 & 63;
                float x0 = (acc[i][j][rr * 2 + 0] + bias[n0 + 0]) * scale;
                float x1 = (acc[i][j][rr * 2 + 1] + bias[n0 + 1]) * scale;
                __nv_bfloat16 h0 = __float2bfloat16(x0);
                __nv_bfloat16 h1 = __float2bfloat16(x1);
                __nv_bfloat16 l0 = __float2bfloat16(x0 - __bfloat162float(h0));
                __nv_bfloat16 l1 = __float2bfloat16(x1 - __bfloat162float(h1));
                if (z == 0) {
                    size_t o = (((size_t)(b * H_ + h) * S_) + sdx) * DK_ + d;
                    __nv_bfloat162 ph; ph.x = h0; ph.y = h1;
                    __nv_bfloat162 pl; pl.x = l0; pl.y = l1;
                    *(__nv_bfloat162*)&g_qh[o] = ph;
                    *(__nv_bfloat162*)&g_ql[o] = pl;
                } else if (z == 1) {
                    size_t o = (((size_t)(b * H_ + h) * S_) + sdx) * DK_ + d;
                    __nv_bfloat162 ph; ph.x = h0; ph.y = h1;
                    __nv_bfloat162 pl; pl.x = l0; pl.y = l1;
                    *(__nv_bfloat162*)&g_kh[o] = ph;
                    *(__nv_bfloat162*)&g_kl[o] = pl;
                } else {
                    size_t o = ((size_t)(b * H_ + h) * DK_ + d) * S_ + sdx;
                    g_vth[o] = h0; g_vth[o + S_] = h1;
                    g_vtl[o] = l0; g_vtl[o + S_] = l1;
                }
            }
        }
    }
}

// ---------------- tensor-core attention -------------------------------------
// BR=128, 3-stage K/V ring, softmax of chunk c overlapped with PV of chunk c-1.
#define BR   128
#define KC   64
#define NCHA (S_ / KC)     // 32
#define QSTR 144           // bytes/row (72 bf16)
#define KMAT (64 * QSTR)   // 9216
#define STG  (4 * KMAT + 256)      // 37120
#define OFFK (2 * BR * QSTR)       // 36864

// ---- macro blocks (textual, so all register arrays stay SROA-promotable) ---
#define SCORES_BLK(KHU)                                                        \
    {                                                                          \
        const uint32_t _kh = (KHU);                                            \
        const uint32_t _kl = _kh + KMAT;                                       \
        _Pragma("unroll")                                                      \
        for (int _n = 0; _n < 8; _n++)                                         \
            _Pragma("unroll")                                                  \
            for (int _r = 0; _r < 4; _r++) accs[_n][_r] = 0.f;                 \
        _Pragma("unroll")                                                      \
        for (int kt = 0; kt < 4; kt++) {                                       \
            _Pragma("unroll")                                                  \
            for (int np = 0; np < 4; np++) {                                   \
                uint32_t off = (uint32_t)(np * 16 * QSTR + kt * 32) + lboff;   \
                uint32_t bh4[4], bl4[4];                                       \
                ldsm4(bh4, _kh + off);                                         \
                ldsm4(bl4, _kl + off);                                         \
                mma_bf16(accs[2*np],   qf[kt][0], qf[kt][1], qf[kt][2], qf[kt][3], bh4[0], bh4[1]); \
                mma_bf16(accs[2*np+1], qf[kt][0], qf[kt][1], qf[kt][2], qf[kt][3], bh4[2], bh4[3]); \
                mma_bf16(accs[2*np],   qf[kt][0], qf[kt][1], qf[kt][2], qf[kt][3], bl4[0], bl4[1]); \
                mma_bf16(accs[2*np+1], qf[kt][0], qf[kt][1], qf[kt][2], qf[kt][3], bl4[2], bl4[3]); \
                mma_bf16(accs[2*np],   qlf[kt][0], qlf[kt][1], qlf[kt][2], qlf[kt][3], bh4[0], bh4[1]); \
                mma_bf16(accs[2*np+1], qlf[kt][0], qlf[kt][1], qlf[kt][2], qlf[kt][3], bh4[2], bh4[3]); \
            }                                                                  \
        }                                                                      \
    }

#define EXP_BLK(PH, PL, MK)                                                    \
    {                                                                          \
        _Pragma("unroll")                                                      \
        for (int nt = 0; nt < 8; nt++) {                                       \
            float m0 = (MK)[nt * 8 + fc];                                      \
            float m1 = (MK)[nt * 8 + fc + 1];                                  \
            _Pragma("unroll")                                                  \
            for (int rr = 0; rr < 2; rr++) {                                   \
                float p0 = __expf(accs[nt][rr * 2 + 0]) * m0;                  \
                float p1 = __expf(accs[nt][rr * 2 + 1]) * m1;                  \
                if (rr == 0) den0 += p0 + p1; else den1 += p0 + p1;            \
                float h0 = bf16_round(p0);                                     \
                float h1 = bf16_round(p1);                                     \
                PH[nt >> 1][(nt & 1) * 2 + rr] = pack_bf16x2(p0, p1);          \
                PL[nt >> 1][(nt & 1) * 2 + rr] = pack_bf16x2(p0 - h0, p1 - h1);\
            }                                                                  \
        }                                                                      \
    }

#define PV_BLK(KHU, PH, PL)                                                    \
    {                                                                          \
        const uint32_t _vh = (KHU) + 2 * KMAT;                                 \
        const uint32_t _vl = (KHU) + 3 * KMAT;                                 \
        _Pragma("unroll")                                                      \
        for (int kt = 0; kt < 4; kt++) {                                       \
            _Pragma("unroll")                                                  \
            for (int np = 0; np < 4; np++) {                                   \
                uint32_t off = (uint32_t)(np * 16 * QSTR + kt * 32) + lboff;   \
                uint32_t vh4[4], vl4[4];                                       \
                ldsm4(vh4, _vh + off);                                         \
                ldsm4(vl4, _vl + off);                                         \
                mma_bf16(accO[2*np],   PH[kt][0], PH[kt][1], PH[kt][2], PH[kt][3], vh4[0], vh4[1]); \
                mma_bf16(accO[2*np+1], PH[kt][0], PH[kt][1], PH[kt][2], PH[kt][3], vh4[2], vh4[3]); \
                mma_bf16(accO[2*np],   PH[kt][0], PH[kt][1], PH[kt][2], PH[kt][3], vl4[0], vl4[1]); \
                mma_bf16(accO[2*np+1], PH[kt][0], PH[kt][1], PH[kt][2], PH[kt][3], vl4[2], vl4[3]); \
                mma_bf16(accO[2*np],   PL[kt][0], PL[kt][1], PL[kt][2], PL[kt][3], vh4[0], vh4[1]); \
                mma_bf16(accO[2*np+1], PL[kt][0], PL[kt][1], PL[kt][2], PL[kt][3], vh4[2], vh4[3]); \
            }                                                                  \
        }                                                                      \
    }

__global__ __launch_bounds__(256, 1) void attn_mma_kernel(
    const float* __restrict__ maskg, float* __restrict__ out)
{
    extern __shared__ char smc[];

    const int tid  = threadIdx.x;
    const int wid  = tid >> 5;
    const int lane = tid & 31;
    const int fr   = lane >> 2;
    const int fc   = (lane & 3) * 2;
    const int lrow = lane & 7;
    const int lm   = lane >> 3;
    const int bh   = blockIdx.y;
    const int b    = bh >> 4;
    const int h    = bh & 15;
    const int bm   = blockIdx.x * BR;
    const int wq0  = wid * 16;

    const __nv_bfloat16* qh_g = g_qh + ((size_t)bh * S_ + bm) * DK_;
    const __nv_bfloat16* ql_g = g_ql + ((size_t)bh * S_ + bm) * DK_;

    // Q loads join chunk 0's commit group
    #pragma unroll
    for (int t = 0; t < 4; t++) {
        int idx = tid + t * 256;          // 0..1023
        int r = idx >> 3, u = idx & 7;
        cp16(smc + r * QSTR + u * 16,              qh_g + r * DK_ + u * 8);
        cp16(smc + BR * QSTR + r * QSTR + u * 16,  ql_g + r * DK_ + u * 8);
    }

    auto load_chunk = [&](int c, int s) {
        const int k0 = c * KC;
        char* st = smc + OFFK + s * STG;
        #pragma unroll
        for (int t = 0; t < 2; t++) {
            int idx = tid + t * 256;      // 0..511
            int r = idx >> 3, u = idx & 7;
            cp16(st + r * QSTR + u * 16,
                 g_kh + ((size_t)bh * S_ + k0 + r) * DK_ + u * 8);
            cp16(st + KMAT + r * QSTR + u * 16,
                 g_kl + ((size_t)bh * S_ + k0 + r) * DK_ + u * 8);
            cp16(st + 2 * KMAT + r * QSTR + u * 16,
                 g_vth + ((size_t)bh * DK_ + r) * S_ + k0 + u * 8);
            cp16(st + 3 * KMAT + r * QSTR + u * 16,
                 g_vtl + ((size_t)bh * DK_ + r) * S_ + k0 + u * 8);
        }
        if (tid < 16) cp16(st + 4 * KMAT + tid * 16, maskg + (size_t)b * S_ + k0 + tid * 4);
        CP_COMMIT();
    };

    load_chunk(0, 0);
    load_chunk(1, 1);

    uint32_t qf[4][4], qlf[4][4];
    float accO[8][4];
    float accs[8][4];
    uint32_t phfA[4][4], plfA[4][4], phfB[4][4], plfB[4][4];
    #pragma unroll
    for (int n = 0; n < 8; n++)
        #pragma unroll
        for (int r = 0; r < 4; r++) accO[n][r] = 0.f;
    float den0 = 0.f, den1 = 0.f;

    const uint32_t smc_u = smem_u32(smc);
    const uint32_t lboff = (uint32_t)(((lm >> 1) * 8 + lrow) * QSTR + (lm & 1) * 16);

    for (int c = 0; c < NCHA; c += 2) {
        // ================= even chunk c: build A, consume B(c-1) =============
        if (c + 1 < NCHA) { CP_WAIT1(); } else { CP_WAIT0(); }
        __syncthreads();

        if (c == 0) {
            const char* qhB = smc;
            const char* qlB = smc + BR * QSTR;
            int r0 = wq0 + fr;
            #pragma unroll
            for (int kt = 0; kt < 4; kt++) {
                int cb = (kt * 16 + fc) * 2;
                qf[kt][0]  = *(const uint32_t*)(qhB + r0 * QSTR + cb);
                qf[kt][1]  = *(const uint32_t*)(qhB + (r0 + 8) * QSTR + cb);
                qf[kt][2]  = *(const uint32_t*)(qhB + r0 * QSTR + cb + 16);
                qf[kt][3]  = *(const uint32_t*)(qhB + (r0 + 8) * QSTR + cb + 16);
                qlf[kt][0] = *(const uint32_t*)(qlB + r0 * QSTR + cb);
                qlf[kt][1] = *(const uint32_t*)(qlB + (r0 + 8) * QSTR + cb);
                qlf[kt][2] = *(const uint32_t*)(qlB + r0 * QSTR + cb + 16);
                qlf[kt][3] = *(const uint32_t*)(qlB + (r0 + 8) * QSTR + cb + 16);
            }
        }

        {
            const uint32_t st0 = smc_u + OFFK + (uint32_t)((c % 3) * STG);
            const float* mk0 = (const float*)(smc + OFFK + (c % 3) * STG + 4 * KMAT);
            SCORES_BLK(st0);
            if (c > 0) {
                const uint32_t stp = smc_u + OFFK + (uint32_t)(((c - 1) % 3) * STG);
                PV_BLK(stp, phfB, plfB);
            }
            EXP_BLK(phfA, plfA, mk0);
        }
        __syncthreads();                       // stage (c-1)%3 fully read
        if (c + 2 < NCHA) load_chunk(c + 2, (c + 2) % 3);

        // ================= odd chunk c+1: build B, consume A(c) ==============
        if (c + 2 < NCHA) { CP_WAIT1(); } else { CP_WAIT0(); }
        __syncthreads();
        {
            const uint32_t st1 = smc_u + OFFK + (uint32_t)(((c + 1) % 3) * STG);
            const float* mk1 = (const float*)(smc + OFFK + ((c + 1) % 3) * STG + 4 * KMAT);
            SCORES_BLK(st1);
            {
                const uint32_t stp = smc_u + OFFK + (uint32_t)((c % 3) * STG);
                PV_BLK(stp, phfA, plfA);
            }
            EXP_BLK(phfB, plfB, mk1);
        }
        __syncthreads();                       // stage c%3 fully read
        if (c + 3 < NCHA) load_chunk(c + 3, (c + 3) % 3);
    }

    // final PV for chunk NCHA-1 (odd -> B set)
    {
        const uint32_t stp = smc_u + OFFK + (uint32_t)(((NCHA - 1) % 3) * STG);
        PV_BLK(stp, phfB, plfB);
    }

    den0 += __shfl_xor_sync(0xffffffffu, den0, 1);
    den0 += __shfl_xor_sync(0xffffffffu, den0, 2);
    den1 += __shfl_xor_sync(0xffffffffu, den1, 1);
    den1 += __shfl_xor_sync(0xffffffffu, den1, 2);
    float inv0 = 1.f / (den0 + 1e-8f);
    float inv1 = 1.f / (den1 + 1e-8f);

    int q = bm + wq0 + fr;
    #pragma unroll
    for (int nt = 0; nt < 8; nt++) {
        int col = h * DK_ + nt * 8 + fc;
        float2 o0; o0.x = accO[nt][0] * inv0; o0.y = accO[nt][1] * inv0;
        float2 o1; o1.x = accO[nt][2] * inv1; o1.y = accO[nt][3] * inv1;
        *(float2*)&out[((size_t)(b * S_ + q)) * N_ + col] = o0;
        *(float2*)&out[((size_t)(b * S_ + q + 8)) * N_ + col] = o1;
    }
}

// ---------------------------------------------------------------------------
extern "C" void kernel_launch(void* const* d_in, const int* in_sizes, int n_in,
                              void* d_out, int out_size)
{
    const float* Q    = (const float*)d_in[0];
    const float* Kin  = (const float*)d_in[1];
    const float* Vin  = (const float*)d_in[2];
    const float* mask = (const float*)d_in[3];
    const float* Wq   = (const float*)d_in[4];
    const float* bq   = (const float*)d_in[5];
    const float* Wk   = (const float*)d_in[6];
    const float* bk   = (const float*)d_in[7];
    const float* Wv   = (const float*)d_in[8];
    const float* bv   = (const float*)d_in[9];
    float* out = (float*)d_out;

    __nv_bfloat16 *xhi, *xlo, *whiT, *wloT;
    cudaGetSymbolAddress((void**)&xhi,  g_xhi);
    cudaGetSymbolAddress((void**)&xlo,  g_xlo);
    cudaGetSymbolAddress((void**)&whiT, g_wThi);
    cudaGetSymbolAddress((void**)&wloT, g_wTlo);

    const int psmem = 2 * STAGE_B;   // 81920
    cudaFuncSetAttribute(proj_all_kernel,
                         cudaFuncAttributeMaxDynamicSharedMemorySize, psmem);

    const int n4 = (M_ * KD_) / 4;
    split_all_kernel<<<dim3((n4 + 255) / 256, 3), 256>>>(
        (const float4*)Q, (const float4*)Kin, (const float4*)Vin,
        (uint2*)xhi, (uint2*)xlo, n4);
    splitT_all_kernel<<<dim3(N_ / 32, KD_ / 32, 3), dim3(32, 8)>>>(
        Wq, Wk, Wv, whiT, wloT);
    proj_all_kernel<<<dim3(N_ / 128, M_ / 128, 3), 256, psmem>>>(bq, bk, bv);

    const int asmem = OFFK + 3 * STG;   // 36864 + 111360 = 148224
    cudaFuncSetAttribute(attn_mma_kernel,
                         cudaFuncAttributeMaxDynamicSharedMemorySize, asmem);
    attn_mma_kernel<<<dim3(S_ / BR, B_ * H_), 256, asmem>>>(mask, out);
}

// round 12
// speedup vs baseline: 1.5701x; 1.5701x over previous
#include <cuda_runtime.h>
#include <cuda_fp16.h>
#include <cstdint>

#define B_  4
#define S_  2048
#define D_  1024
#define H_  16
#define DK_ 64
#define M_  (B_*S_)    // 8192
#define N_  (H_*DK_)   // 1024
#define KD_ D_         // 1024

// ---------------- device scratch (allocation-free rule: device globals) ----
__device__ __half g_xhi[3*M_*KD_];      // per z: Q,K,V inputs split
__device__ __half g_xlo[3*M_*KD_];
__device__ __half g_wThi[3*N_*KD_];     // per z: W transposed [n][k]
__device__ __half g_wTlo[3*N_*KD_];
__device__ __half g_qh[B_*H_*S_*DK_];   // [bh][s][64]
__device__ __half g_kh[B_*H_*S_*DK_];
__device__ __half g_vth[B_*H_*DK_*S_];  // V^T: [bh][d][s]

// ---------------- helpers ---------------------------------------------------
__device__ __forceinline__ uint32_t smem_u32(const void* p) {
    uint32_t a;
    asm("{ .reg .u64 t; cvta.to.shared.u64 t, %1; cvt.u32.u64 %0, t; }"
        : "=r"(a) : "l"(p));
    return a;
}
__device__ __forceinline__ void cp16(void* dst, const void* src) {
    asm volatile("cp.async.cg.shared.global [%0], [%1], 16;"
                 :: "r"(smem_u32(dst)), "l"(src));
}
#define CP_COMMIT() asm volatile("cp.async.commit_group;" ::: "memory")
#define CP_WAIT1()  asm volatile("cp.async.wait_group 1;" ::: "memory")
#define CP_WAIT0()  asm volatile("cp.async.wait_group 0;" ::: "memory")

__device__ __forceinline__ void mma_f16(float* d,
                                        uint32_t a0, uint32_t a1, uint32_t a2, uint32_t a3,
                                        uint32_t b0, uint32_t b1)
{
    asm volatile(
        "mma.sync.aligned.m16n8k16.row.col.f32.f16.f16.f32 "
        "{%0,%1,%2,%3}, {%4,%5,%6,%7}, {%8,%9}, {%0,%1,%2,%3};"
        : "+f"(d[0]), "+f"(d[1]), "+f"(d[2]), "+f"(d[3])
        : "r"(a0), "r"(a1), "r"(a2), "r"(a3), "r"(b0), "r"(b1));
}
__device__ __forceinline__ void ldsm4(uint32_t* r, uint32_t addr) {
    asm volatile("ldmatrix.sync.aligned.m8n8.x4.shared.b16 {%0,%1,%2,%3}, [%4];"
                 : "=r"(r[0]), "=r"(r[1]), "=r"(r[2]), "=r"(r[3]) : "r"(addr));
}
__device__ __forceinline__ uint32_t pack_f16x2(float lo, float hi) {
    uint32_t r;
    asm("cvt.rn.f16x2.f32 %0, %1, %2;" : "=r"(r) : "f"(hi), "f"(lo));
    return r;
}
__device__ __forceinline__ float f16_round(float x) {
    return __half2float(__float2half(x));
}

// ---------------- batched fp32 -> fp16 hi/lo split ---------------------------
__global__ void split_all_kernel(const float4* __restrict__ x0,
                                 const float4* __restrict__ x1,
                                 const float4* __restrict__ x2,
                                 uint2* __restrict__ hi,
                                 uint2* __restrict__ lo, int n4)
{
    int i = blockIdx.x * blockDim.x + threadIdx.x;
    int z = blockIdx.y;
    if (i < n4) {
        const float4* x = (z == 0) ? x0 : (z == 1) ? x1 : x2;
        float4 v = x[i];
        uint2 h, l;
        h.x = pack_f16x2(v.x, v.y);
        h.y = pack_f16x2(v.z, v.w);
        l.x = pack_f16x2(v.x - f16_round(v.x), v.y - f16_round(v.y));
        l.y = pack_f16x2(v.z - f16_round(v.z), v.w - f16_round(v.w));
        hi[(size_t)z * n4 + i] = h;
        lo[(size_t)z * n4 + i] = l;
    }
}

// batched W [K][N] -> transposed hi/lo [N][K]; z = blockIdx.z
__global__ __launch_bounds__(256) void splitT_all_kernel(
    const float* __restrict__ w0, const float* __restrict__ w1,
    const float* __restrict__ w2,
    __half* __restrict__ hiT, __half* __restrict__ loT)
{
    __shared__ float t[32][33];
    const int tx = threadIdx.x;
    const int ty = threadIdx.y;
    const int k0 = blockIdx.y * 32;
    const int n0 = blockIdx.x * 32;
    const int z  = blockIdx.z;
    const float* w = (z == 0) ? w0 : (z == 1) ? w1 : w2;
    const size_t zo = (size_t)z * N_ * KD_;
    #pragma unroll
    for (int i = 0; i < 4; i++)
        t[ty + i * 8][tx] = w[(size_t)(k0 + ty + i * 8) * N_ + n0 + tx];
    __syncthreads();
    #pragma unroll
    for (int i = 0; i < 4; i++) {
        int n = n0 + ty + i * 8;
        int k = k0 + tx;
        float v = t[tx][ty + i * 8];
        __half h = __float2half(v);
        hiT[zo + (size_t)n * KD_ + k] = h;
        loT[zo + (size_t)n * KD_ + k] = __float2half(v - __half2float(h));
    }
}

// ---------------- batched split-precision fp16 projection GEMM --------------
// Full 3-term split precision (errors here are coherent in q/k/v values).
#define PAD      40
#define MAT_B    (128 * PAD * 2)
#define STAGE_B  (4 * MAT_B)
#define NKCH     (KD_ / 32)

__global__ __launch_bounds__(256, 2) void proj_all_kernel(
    const float* __restrict__ bq, const float* __restrict__ bk,
    const float* __restrict__ bv)
{
    extern __shared__ char psm[];

    const int tid  = threadIdx.x;
    const int wid  = tid >> 5;
    const int lane = tid & 31;
    const int wm   = wid >> 2;
    const int wn   = wid & 3;
    const int bm   = blockIdx.y * 128;
    const int bn   = blockIdx.x * 128;
    const int z    = blockIdx.z;

    const __half* xhi  = g_xhi  + (size_t)z * M_ * KD_;
    const __half* xlo  = g_xlo  + (size_t)z * M_ * KD_;
    const __half* whiT = g_wThi + (size_t)z * N_ * KD_;
    const __half* wloT = g_wTlo + (size_t)z * N_ * KD_;
    const float* bias = (z == 0) ? bq : (z == 1) ? bk : bv;
    const float scale = (z == 0) ? 0.125f : 1.0f;

    float acc[4][4][4];
    #pragma unroll
    for (int i = 0; i < 4; i++)
        #pragma unroll
        for (int j = 0; j < 4; j++)
            #pragma unroll
            for (int r = 0; r < 4; r++) acc[i][j][r] = 0.f;

    auto load_stage = [&](int c, int s) {
        const int k0 = c * 32;
        char* st = psm + s * STAGE_B;
        #pragma unroll
        for (int t = 0; t < 8; t++) {
            int idx = tid + t * 256;
            int mat = idx >> 9;
            int rr  = (idx >> 2) & 127;
            int u   = idx & 3;
            const __half* src =
                (mat == 0) ? xhi : (mat == 1) ? xlo : (mat == 2) ? whiT : wloT;
            size_t off = (mat < 2)
                ? (size_t)(bm + rr) * KD_ + k0 + u * 8
                : (size_t)(bn + rr) * KD_ + k0 + u * 8;
            cp16(st + mat * MAT_B + rr * (PAD * 2) + u * 16, src + off);
        }
        CP_COMMIT();
    };

    const int fr   = lane >> 2;
    const int fc   = (lane & 3) * 2;
    const int lrow = lane & 7;
    const int lm   = lane >> 3;
    const uint32_t psm_u = smem_u32(psm);

    auto compute = [&](int s) {
        const uint32_t aHi = psm_u + s * STAGE_B;
        const uint32_t aLo = aHi + MAT_B;
        const uint32_t bHi = aHi + 2 * MAT_B;
        const uint32_t bLo = aHi + 3 * MAT_B;
        #pragma unroll
        for (int ks = 0; ks < 2; ks++) {
            const int kc = ks * 16;
            const uint32_t aoff = (uint32_t)(((lm & 1) * 8 + lrow) * (PAD * 2)
                                             + (kc + (lm >> 1) * 8) * 2);
            const uint32_t boff = (uint32_t)(((lm >> 1) * 8 + lrow) * (PAD * 2)
                                             + (kc + (lm & 1) * 8) * 2);
            uint32_t af[4][4], al[4][4], bh[8], bl[8];
            #pragma unroll
            for (int i = 0; i < 4; i++) {
                uint32_t ra = (uint32_t)((wm * 64 + i * 16) * (PAD * 2));
                ldsm4(af[i], aHi + ra + aoff);
                ldsm4(al[i], aLo + ra + aoff);
            }
            #pragma unroll
            for (int jb = 0; jb < 2; jb++) {
                uint32_t rb = (uint32_t)((wn * 32 + jb * 16) * (PAD * 2));
                ldsm4(&bh[jb * 4], bHi + rb + boff);
                ldsm4(&bl[jb * 4], bLo + rb + boff);
            }
            #pragma unroll
            for (int i = 0; i < 4; i++)
                #pragma unroll
                for (int j = 0; j < 4; j++) {
                    mma_f16(acc[i][j], af[i][0], af[i][1], af[i][2], af[i][3],
                            bh[j * 2], bh[j * 2 + 1]);
                    mma_f16(acc[i][j], af[i][0], af[i][1], af[i][2], af[i][3],
                            bl[j * 2], bl[j * 2 + 1]);
                    mma_f16(acc[i][j], al[i][0], al[i][1], al[i][2], al[i][3],
                            bh[j * 2], bh[j * 2 + 1]);
                }
        }
    };

    load_stage(0, 0);
    for (int c = 0; c < NKCH; c++) {
        const int s = c & 1;
        if (c + 1 < NKCH) load_stage(c + 1, s ^ 1);
        if (c + 1 < NKCH) { CP_WAIT1(); } else { CP_WAIT0(); }
        __syncthreads();
        compute(s);
        __syncthreads();
    }

    // epilogue: bias+scale, round to fp16, write (V transposed when z==2)
    #pragma unroll
    for (int i = 0; i < 4; i++) {
        #pragma unroll
        for (int rr = 0; rr < 2; rr++) {
            int m = bm + wm * 64 + i * 16 + fr + rr * 8;
            int b = m >> 11;
            int sdx = m & (S_ - 1);
            #pragma unroll
            for (int j = 0; j < 4; j++) {
                int n0 = bn + wn * 32 + j * 8 + fc;
                int h  = n0 >> 6;
                int d  = n0 & 63;
                float x0 = (acc[i][j][rr * 2 + 0] + bias[n0 + 0]) * scale;
                float x1 = (acc[i][j][rr * 2 + 1] + bias[n0 + 1]) * scale;
                __half h0 = __float2half(x0);
                __half h1 = __float2half(x1);
                if (z == 0) {
                    size_t o = (((size_t)(b * H_ + h) * S_) + sdx) * DK_ + d;
                    __half2 ph; ph.x = h0; ph.y = h1;
                    *(__half2*)&g_qh[o] = ph;
                } else if (z == 1) {
                    size_t o = (((size_t)(b * H_ + h) * S_) + sdx) * DK_ + d;
                    __half2 ph; ph.x = h0; ph.y = h1;
                    *(__half2*)&g_kh[o] = ph;
                } else {
                    size_t o = ((size_t)(b * H_ + h) * DK_ + d) * S_ + sdx;
                    g_vth[o] = h0; g_vth[o + S_] = h1;
                }
            }
        }
    }
}

// ---------------- tensor-core attention (pure fp16, BR=128) -----------------
#define BR   128
#define KC   64
#define NCHA (S_ / KC)     // 32
#define QSTR 144           // bytes/row (72 halves)
#define KMAT (64 * QSTR)   // 9216
#define STG  (2 * KMAT + 256)      // 18688 (kh + vh + mask)
#define OFFK (BR * QSTR)           // 18432 (after qh)

__global__ __launch_bounds__(256, 2) void attn_mma_kernel(
    const float* __restrict__ maskg, float* __restrict__ out)
{
    extern __shared__ char smc[];

    const int tid  = threadIdx.x;
    const int wid  = tid >> 5;
    const int lane = tid & 31;
    const int fr   = lane >> 2;
    const int fc   = (lane & 3) * 2;
    const int lrow = lane & 7;
    const int lm   = lane >> 3;
    const int bh   = blockIdx.y;
    const int b    = bh >> 4;
    const int h    = bh & 15;
    const int bm   = blockIdx.x * BR;
    const int wq0  = wid * 16;

    const __half* qh_g = g_qh + ((size_t)bh * S_ + bm) * DK_;

    // Q load (joins chunk 0's commit group): 1024 16B units
    #pragma unroll
    for (int t = 0; t < 4; t++) {
        int idx = tid + t * 256;
        int r = idx >> 3, u = idx & 7;
        cp16(smc + r * QSTR + u * 16, qh_g + r * DK_ + u * 8);
    }

    auto load_chunk = [&](int c, int s) {
        const int k0 = c * KC;
        char* st = smc + OFFK + s * STG;
        #pragma unroll
        for (int t = 0; t < 2; t++) {
            int idx = tid + t * 256;      // 0..511 : 64 rows x 8 units
            int r = idx >> 3, u = idx & 7;
            cp16(st + r * QSTR + u * 16,
                 g_kh + ((size_t)bh * S_ + k0 + r) * DK_ + u * 8);
            cp16(st + KMAT + r * QSTR + u * 16,
                 g_vth + ((size_t)bh * DK_ + r) * S_ + k0 + u * 8);
        }
        if (tid < 16) cp16(st + 2 * KMAT + tid * 16, maskg + (size_t)b * S_ + k0 + tid * 4);
        CP_COMMIT();
    };

    load_chunk(0, 0);

    uint32_t qf[4][4];
    float accO[8][4];
    #pragma unroll
    for (int n = 0; n < 8; n++)
        #pragma unroll
        for (int r = 0; r < 4; r++) accO[n][r] = 0.f;
    float den0 = 0.f, den1 = 0.f;

    const uint32_t smc_u = smem_u32(smc);
    const uint32_t lboff = (uint32_t)(((lm >> 1) * 8 + lrow) * QSTR + (lm & 1) * 16);

    for (int c = 0; c < NCHA; c++) {
        const int s = c & 1;
        if (c + 1 < NCHA) load_chunk(c + 1, s ^ 1);
        if (c + 1 < NCHA) { CP_WAIT1(); } else { CP_WAIT0(); }
        __syncthreads();

        if (c == 0) {
            const char* qhB = smc;
            int r0 = wq0 + fr;
            #pragma unroll
            for (int kt = 0; kt < 4; kt++) {
                int cb = (kt * 16 + fc) * 2;
                qf[kt][0] = *(const uint32_t*)(qhB + r0 * QSTR + cb);
                qf[kt][1] = *(const uint32_t*)(qhB + (r0 + 8) * QSTR + cb);
                qf[kt][2] = *(const uint32_t*)(qhB + r0 * QSTR + cb + 16);
                qf[kt][3] = *(const uint32_t*)(qhB + (r0 + 8) * QSTR + cb + 16);
            }
        }

        const uint32_t khu = smc_u + OFFK + (uint32_t)(s * STG);
        const uint32_t vhu = khu + KMAT;
        const float* mk = (const float*)(smc + OFFK + s * STG + 2 * KMAT);

        // ---- scores (fp16, 1 term)
        float accs[8][4];
        #pragma unroll
        for (int n = 0; n < 8; n++)
            #pragma unroll
            for (int r = 0; r < 4; r++) accs[n][r] = 0.f;

        #pragma unroll
        for (int kt = 0; kt < 4; kt++) {
            #pragma unroll
            for (int np = 0; np < 4; np++) {
                uint32_t off = (uint32_t)(np * 16 * QSTR + kt * 32) + lboff;
                uint32_t bh4[4];
                ldsm4(bh4, khu + off);
                mma_f16(accs[2*np],   qf[kt][0], qf[kt][1], qf[kt][2], qf[kt][3], bh4[0], bh4[1]);
                mma_f16(accs[2*np+1], qf[kt][0], qf[kt][1], qf[kt][2], qf[kt][3], bh4[2], bh4[3]);
            }
        }

        // ---- P = exp(s) * mask; fp16 pack; denom (fp32, pre-rounding)
        uint32_t phf[4][4];
        #pragma unroll
        for (int nt = 0; nt < 8; nt++) {
            float m0 = mk[nt * 8 + fc];
            float m1 = mk[nt * 8 + fc + 1];
            #pragma unroll
            for (int rr = 0; rr < 2; rr++) {
                float p0 = __expf(accs[nt][rr * 2 + 0]) * m0;
                float p1 = __expf(accs[nt][rr * 2 + 1]) * m1;
                if (rr == 0) den0 += p0 + p1; else den1 += p0 + p1;
                phf[nt >> 1][(nt & 1) * 2 + rr] = pack_f16x2(p0, p1);
            }
        }

        // ---- O += P @ V (fp16, 1 term)
        #pragma unroll
        for (int kt = 0; kt < 4; kt++) {
            #pragma unroll
            for (int np = 0; np < 4; np++) {
                uint32_t off = (uint32_t)(np * 16 * QSTR + kt * 32) + lboff;
                uint32_t vh4[4];
                ldsm4(vh4, vhu + off);
                mma_f16(accO[2*np],   phf[kt][0], phf[kt][1], phf[kt][2], phf[kt][3], vh4[0], vh4[1]);
                mma_f16(accO[2*np+1], phf[kt][0], phf[kt][1], phf[kt][2], phf[kt][3], vh4[2], vh4[3]);
            }
        }
        __syncthreads();
    }

    den0 += __shfl_xor_sync(0xffffffffu, den0, 1);
    den0 += __shfl_xor_sync(0xffffffffu, den0, 2);
    den1 += __shfl_xor_sync(0xffffffffu, den1, 1);
    den1 += __shfl_xor_sync(0xffffffffu, den1, 2);
    float inv0 = 1.f / (den0 + 1e-8f);
    float inv1 = 1.f / (den1 + 1e-8f);

    int q = bm + wq0 + fr;
    #pragma unroll
    for (int nt = 0; nt < 8; nt++) {
        int col = h * DK_ + nt * 8 + fc;
        float2 o0; o0.x = accO[nt][0] * inv0; o0.y = accO[nt][1] * inv0;
        float2 o1; o1.x = accO[nt][2] * inv1; o1.y = accO[nt][3] * inv1;
        *(float2*)&out[((size_t)(b * S_ + q)) * N_ + col] = o0;
        *(float2*)&out[((size_t)(b * S_ + q + 8)) * N_ + col] = o1;
    }
}

// ---------------------------------------------------------------------------
extern "C" void kernel_launch(void* const* d_in, const int* in_sizes, int n_in,
                              void* d_out, int out_size)
{
    const float* Q    = (const float*)d_in[0];
    const float* Kin  = (const float*)d_in[1];
    const float* Vin  = (const float*)d_in[2];
    const float* mask = (const float*)d_in[3];
    const float* Wq   = (const float*)d_in[4];
    const float* bq   = (const float*)d_in[5];
    const float* Wk   = (const float*)d_in[6];
    const float* bk   = (const float*)d_in[7];
    const float* Wv   = (const float*)d_in[8];
    const float* bv   = (const float*)d_in[9];
    float* out = (float*)d_out;

    __half *xhi, *xlo, *whiT, *wloT;
    cudaGetSymbolAddress((void**)&xhi,  g_xhi);
    cudaGetSymbolAddress((void**)&xlo,  g_xlo);
    cudaGetSymbolAddress((void**)&whiT, g_wThi);
    cudaGetSymbolAddress((void**)&wloT, g_wTlo);

    const int psmem = 2 * STAGE_B;   // 81920
    cudaFuncSetAttribute(proj_all_kernel,
                         cudaFuncAttributeMaxDynamicSharedMemorySize, psmem);

    const int n4 = (M_ * KD_) / 4;
    split_all_kernel<<<dim3((n4 + 255) / 256, 3), 256>>>(
        (const float4*)Q, (const float4*)Kin, (const float4*)Vin,
        (uint2*)xhi, (uint2*)xlo, n4);
    splitT_all_kernel<<<dim3(N_ / 32, KD_ / 32, 3), dim3(32, 8)>>>(
        Wq, Wk, Wv, whiT, wloT);
    proj_all_kernel<<<dim3(N_ / 128, M_ / 128, 3), 256, psmem>>>(bq, bk, bv);

    const int asmem = OFFK + 2 * STG;   // 18432 + 37376 = 55808
    cudaFuncSetAttribute(attn_mma_kernel,
                         cudaFuncAttributeMaxDynamicSharedMemorySize, asmem);
    attn_mma_kernel<<<dim3(S_ / BR, B_ * H_), 256, asmem>>>(mask, out);
}

// round 13
// speedup vs baseline: 1.9429x; 1.2374x over previous
#include <cuda_runtime.h>
#include <cuda_fp16.h>
#include <cstdint>

#define B_  4
#define S_  2048
#define D_  1024
#define H_  16
#define DK_ 64
#define M_  (B_*S_)    // 8192
#define N_  (H_*DK_)   // 1024
#define KD_ D_         // 1024

// ---------------- device scratch (allocation-free rule: device globals) ----
__device__ __half g_xhi[3*M_*KD_];      // per z: Q,K,V inputs fp16
__device__ __half g_wThi[3*N_*KD_];     // per z: W transposed [n][k]
__device__ __half g_wTlo[3*N_*KD_];
__device__ __half g_qh[B_*H_*S_*DK_];   // [bh][s][64]
__device__ __half g_kh[B_*H_*S_*DK_];
__device__ __half g_vth[B_*H_*DK_*S_];  // V^T: [bh][d][s]

// ---------------- helpers ---------------------------------------------------
__device__ __forceinline__ uint32_t smem_u32(const void* p) {
    uint32_t a;
    asm("{ .reg .u64 t; cvta.to.shared.u64 t, %1; cvt.u32.u64 %0, t; }"
        : "=r"(a) : "l"(p));
    return a;
}
__device__ __forceinline__ void cp16(void* dst, const void* src) {
    asm volatile("cp.async.cg.shared.global [%0], [%1], 16;"
                 :: "r"(smem_u32(dst)), "l"(src));
}
#define CP_COMMIT() asm volatile("cp.async.commit_group;" ::: "memory")
#define CP_WAIT1()  asm volatile("cp.async.wait_group 1;" ::: "memory")
#define CP_WAIT0()  asm volatile("cp.async.wait_group 0;" ::: "memory")

__device__ __forceinline__ void mma_f16(float* d,
                                        uint32_t a0, uint32_t a1, uint32_t a2, uint32_t a3,
                                        uint32_t b0, uint32_t b1)
{
    asm volatile(
        "mma.sync.aligned.m16n8k16.row.col.f32.f16.f16.f32 "
        "{%0,%1,%2,%3}, {%4,%5,%6,%7}, {%8,%9}, {%0,%1,%2,%3};"
        : "+f"(d[0]), "+f"(d[1]), "+f"(d[2]), "+f"(d[3])
        : "r"(a0), "r"(a1), "r"(a2), "r"(a3), "r"(b0), "r"(b1));
}
__device__ __forceinline__ void ldsm4(uint32_t* r, uint32_t addr) {
    asm volatile("ldmatrix.sync.aligned.m8n8.x4.shared.b16 {%0,%1,%2,%3}, [%4];"
                 : "=r"(r[0]), "=r"(r[1]), "=r"(r[2]), "=r"(r[3]) : "r"(addr));
}
__device__ __forceinline__ uint32_t pack_f16x2(float lo, float hi) {
    uint32_t r;
    asm("cvt.rn.f16x2.f32 %0, %1, %2;" : "=r"(r) : "f"(hi), "f"(lo));
    return r;
}

// ---------------- batched fp32 -> fp16 convert (hi only) ---------------------
__global__ void split_all_kernel(const float4* __restrict__ x0,
                                 const float4* __restrict__ x1,
                                 const float4* __restrict__ x2,
                                 uint2* __restrict__ hi, int n4)
{
    int i = blockIdx.x * blockDim.x + threadIdx.x;
    int z = blockIdx.y;
    if (i < n4) {
        const float4* x = (z == 0) ? x0 : (z == 1) ? x1 : x2;
        float4 v = x[i];
        uint2 h;
        h.x = pack_f16x2(v.x, v.y);
        h.y = pack_f16x2(v.z, v.w);
        hi[(size_t)z * n4 + i] = h;
    }
}

// batched W [K][N] -> transposed hi/lo [N][K]; z = blockIdx.z
__global__ __launch_bounds__(256) void splitT_all_kernel(
    const float* __restrict__ w0, const float* __restrict__ w1,
    const float* __restrict__ w2,
    __half* __restrict__ hiT, __half* __restrict__ loT)
{
    __shared__ float t[32][33];
    const int tx = threadIdx.x;
    const int ty = threadIdx.y;
    const int k0 = blockIdx.y * 32;
    const int n0 = blockIdx.x * 32;
    const int z  = blockIdx.z;
    const float* w = (z == 0) ? w0 : (z == 1) ? w1 : w2;
    const size_t zo = (size_t)z * N_ * KD_;
    #pragma unroll
    for (int i = 0; i < 4; i++)
        t[ty + i * 8][tx] = w[(size_t)(k0 + ty + i * 8) * N_ + n0 + tx];
    __syncthreads();
    #pragma unroll
    for (int i = 0; i < 4; i++) {
        int n = n0 + ty + i * 8;
        int k = k0 + tx;
        float v = t[tx][ty + i * 8];
        __half h = __float2half(v);
        hiT[zo + (size_t)n * KD_ + k] = h;
        loT[zo + (size_t)n * KD_ + k] = __float2half(v - __half2float(h));
    }
}

// ---------------- batched 2-term fp16 projection GEMM -----------------------
// q = xhi*(whi + wlo): corrects W rounding; X rounding residual ~2.4e-4 accepted.
#define PAD      40
#define MAT_B    (128 * PAD * 2)
#define STAGE_B  (3 * MAT_B)
#define NKCH     (KD_ / 32)

__global__ __launch_bounds__(256, 2) void proj_all_kernel(
    const float* __restrict__ bq, const float* __restrict__ bk,
    const float* __restrict__ bv)
{
    extern __shared__ char psm[];

    const int tid  = threadIdx.x;
    const int wid  = tid >> 5;
    const int lane = tid & 31;
    const int wm   = wid >> 2;
    const int wn   = wid & 3;
    const int bm   = blockIdx.y * 128;
    const int bn   = blockIdx.x * 128;
    const int z    = blockIdx.z;

    const __half* xhi  = g_xhi  + (size_t)z * M_ * KD_;
    const __half* whiT = g_wThi + (size_t)z * N_ * KD_;
    const __half* wloT = g_wTlo + (size_t)z * N_ * KD_;
    const float* bias = (z == 0) ? bq : (z == 1) ? bk : bv;
    const float scale = (z == 0) ? 0.125f : 1.0f;

    float acc[4][4][4];
    #pragma unroll
    for (int i = 0; i < 4; i++)
        #pragma unroll
        for (int j = 0; j < 4; j++)
            #pragma unroll
            for (int r = 0; r < 4; r++) acc[i][j][r] = 0.f;

    // 3 matrices x 128 rows x 4 16B-units = 1536 units -> 6 iters x 256 thr
    auto load_stage = [&](int c, int s) {
        const int k0 = c * 32;
        char* st = psm + s * STAGE_B;
        #pragma unroll
        for (int t = 0; t < 6; t++) {
            int idx = tid + t * 256;
            int mat = idx >> 9;               // 0:aHi 1:bHi 2:bLo
            int rr  = (idx >> 2) & 127;
            int u   = idx & 3;
            const __half* src = (mat == 0) ? xhi : (mat == 1) ? whiT : wloT;
            size_t off = (mat == 0)
                ? (size_t)(bm + rr) * KD_ + k0 + u * 8
                : (size_t)(bn + rr) * KD_ + k0 + u * 8;
            cp16(st + mat * MAT_B + rr * (PAD * 2) + u * 16, src + off);
        }
        CP_COMMIT();
    };

    const int fr   = lane >> 2;
    const int fc   = (lane & 3) * 2;
    const int lrow = lane & 7;
    const int lm   = lane >> 3;
    const uint32_t psm_u = smem_u32(psm);

    auto compute = [&](int s) {
        const uint32_t aHi = psm_u + s * STAGE_B;
        const uint32_t bHi = aHi + MAT_B;
        const uint32_t bLo = aHi + 2 * MAT_B;
        #pragma unroll
        for (int ks = 0; ks < 2; ks++) {
            const int kc = ks * 16;
            const uint32_t aoff = (uint32_t)(((lm & 1) * 8 + lrow) * (PAD * 2)
                                             + (kc + (lm >> 1) * 8) * 2);
            const uint32_t boff = (uint32_t)(((lm >> 1) * 8 + lrow) * (PAD * 2)
                                             + (kc + (lm & 1) * 8) * 2);
            uint32_t af[4][4], bh[8], bl[8];
            #pragma unroll
            for (int i = 0; i < 4; i++) {
                uint32_t ra = (uint32_t)((wm * 64 + i * 16) * (PAD * 2));
                ldsm4(af[i], aHi + ra + aoff);
            }
            #pragma unroll
            for (int jb = 0; jb < 2; jb++) {
                uint32_t rb = (uint32_t)((wn * 32 + jb * 16) * (PAD * 2));
                ldsm4(&bh[jb * 4], bHi + rb + boff);
                ldsm4(&bl[jb * 4], bLo + rb + boff);
            }
            #pragma unroll
            for (int i = 0; i < 4; i++)
                #pragma unroll
                for (int j = 0; j < 4; j++) {
                    mma_f16(acc[i][j], af[i][0], af[i][1], af[i][2], af[i][3],
                            bh[j * 2], bh[j * 2 + 1]);
                    mma_f16(acc[i][j], af[i][0], af[i][1], af[i][2], af[i][3],
                            bl[j * 2], bl[j * 2 + 1]);
                }
        }
    };

    load_stage(0, 0);
    for (int c = 0; c < NKCH; c++) {
        const int s = c & 1;
        if (c + 1 < NKCH) load_stage(c + 1, s ^ 1);
        if (c + 1 < NKCH) { CP_WAIT1(); } else { CP_WAIT0(); }
        __syncthreads();
        compute(s);
        __syncthreads();
    }

    // epilogue: bias+scale, round to fp16, write (V transposed when z==2)
    #pragma unroll
    for (int i = 0; i < 4; i++) {
        #pragma unroll
        for (int rr = 0; rr < 2; rr++) {
            int m = bm + wm * 64 + i * 16 + fr + rr * 8;
            int b = m >> 11;
            int sdx = m & (S_ - 1);
            #pragma unroll
            for (int j = 0; j < 4; j++) {
                int n0 = bn + wn * 32 + j * 8 + fc;
                int h  = n0 >> 6;
                int d  = n0 & 63;
                float x0 = (acc[i][j][rr * 2 + 0] + bias[n0 + 0]) * scale;
                float x1 = (acc[i][j][rr * 2 + 1] + bias[n0 + 1]) * scale;
                __half h0 = __float2half(x0);
                __half h1 = __float2half(x1);
                if (z == 0) {
                    size_t o = (((size_t)(b * H_ + h) * S_) + sdx) * DK_ + d;
                    __half2 ph; ph.x = h0; ph.y = h1;
                    *(__half2*)&g_qh[o] = ph;
                } else if (z == 1) {
                    size_t o = (((size_t)(b * H_ + h) * S_) + sdx) * DK_ + d;
                    __half2 ph; ph.x = h0; ph.y = h1;
                    *(__half2*)&g_kh[o] = ph;
                } else {
                    size_t o = ((size_t)(b * H_ + h) * DK_ + d) * S_ + sdx;
                    g_vth[o] = h0; g_vth[o + S_] = h1;
                }
            }
        }
    }
}

// ---------------- tensor-core attention (pure fp16, BR=128) -----------------
#define BR   128
#define KC   64
#define NCHA (S_ / KC)     // 32
#define QSTR 144           // bytes/row (72 halves)
#define KMAT (64 * QSTR)   // 9216
#define STG  (2 * KMAT + 256)      // 18688 (kh + vh + mask)
#define OFFK (BR * QSTR)           // 18432 (after qh)

__global__ __launch_bounds__(256, 2) void attn_mma_kernel(
    const float* __restrict__ maskg, float* __restrict__ out)
{
    extern __shared__ char smc[];

    const int tid  = threadIdx.x;
    const int wid  = tid >> 5;
    const int lane = tid & 31;
    const int fr   = lane >> 2;
    const int fc   = (lane & 3) * 2;
    const int lrow = lane & 7;
    const int lm   = lane >> 3;
    const int bh   = blockIdx.y;
    const int b    = bh >> 4;
    const int h    = bh & 15;
    const int bm   = blockIdx.x * BR;
    const int wq0  = wid * 16;

    const __half* qh_g = g_qh + ((size_t)bh * S_ + bm) * DK_;

    // Q load (joins chunk 0's commit group): 1024 16B units
    #pragma unroll
    for (int t = 0; t < 4; t++) {
        int idx = tid + t * 256;
        int r = idx >> 3, u = idx & 7;
        cp16(smc + r * QSTR + u * 16, qh_g + r * DK_ + u * 8);
    }

    auto load_chunk = [&](int c, int s) {
        const int k0 = c * KC;
        char* st = smc + OFFK + s * STG;
        #pragma unroll
        for (int t = 0; t < 2; t++) {
            int idx = tid + t * 256;      // 0..511 : 64 rows x 8 units
            int r = idx >> 3, u = idx & 7;
            cp16(st + r * QSTR + u * 16,
                 g_kh + ((size_t)bh * S_ + k0 + r) * DK_ + u * 8);
            cp16(st + KMAT + r * QSTR + u * 16,
                 g_vth + ((size_t)bh * DK_ + r) * S_ + k0 + u * 8);
        }
        if (tid < 16) cp16(st + 2 * KMAT + tid * 16, maskg + (size_t)b * S_ + k0 + tid * 4);
        CP_COMMIT();
    };

    load_chunk(0, 0);

    uint32_t qf[4][4];
    float accO[8][4];
    #pragma unroll
    for (int n = 0; n < 8; n++)
        #pragma unroll
        for (int r = 0; r < 4; r++) accO[n][r] = 0.f;
    float den0 = 0.f, den1 = 0.f;

    const uint32_t smc_u = smem_u32(smc);
    const uint32_t lboff = (uint32_t)(((lm >> 1) * 8 + lrow) * QSTR + (lm & 1) * 16);

    for (int c = 0; c < NCHA; c++) {
        const int s = c & 1;
        if (c + 1 < NCHA) load_chunk(c + 1, s ^ 1);
        if (c + 1 < NCHA) { CP_WAIT1(); } else { CP_WAIT0(); }
        __syncthreads();

        if (c == 0) {
            const char* qhB = smc;
            int r0 = wq0 + fr;
            #pragma unroll
            for (int kt = 0; kt < 4; kt++) {
                int cb = (kt * 16 + fc) * 2;
                qf[kt][0] = *(const uint32_t*)(qhB + r0 * QSTR + cb);
                qf[kt][1] = *(const uint32_t*)(qhB + (r0 + 8) * QSTR + cb);
                qf[kt][2] = *(const uint32_t*)(qhB + r0 * QSTR + cb + 16);
                qf[kt][3] = *(const uint32_t*)(qhB + (r0 + 8) * QSTR + cb + 16);
            }
        }

        const uint32_t khu = smc_u + OFFK + (uint32_t)(s * STG);
        const uint32_t vhu = khu + KMAT;
        const float* mk = (const float*)(smc + OFFK + s * STG + 2 * KMAT);

        // ---- scores (fp16, 1 term)
        float accs[8][4];
        #pragma unroll
        for (int n = 0; n < 8; n++)
            #pragma unroll
            for (int r = 0; r < 4; r++) accs[n][r] = 0.f;

        #pragma unroll
        for (int kt = 0; kt < 4; kt++) {
            #pragma unroll
            for (int np = 0; np < 4; np++) {
                uint32_t off = (uint32_t)(np * 16 * QSTR + kt * 32) + lboff;
                uint32_t bh4[4];
                ldsm4(bh4, khu + off);
                mma_f16(accs[2*np],   qf[kt][0], qf[kt][1], qf[kt][2], qf[kt][3], bh4[0], bh4[1]);
                mma_f16(accs[2*np+1], qf[kt][0], qf[kt][1], qf[kt][2], qf[kt][3], bh4[2], bh4[3]);
            }
        }

        // ---- P = exp(s) * mask; fp16 pack; denom (fp32, pre-rounding)
        uint32_t phf[4][4];
        #pragma unroll
        for (int nt = 0; nt < 8; nt++) {
            float m0 = mk[nt * 8 + fc];
            float m1 = mk[nt * 8 + fc + 1];
            #pragma unroll
            for (int rr = 0; rr < 2; rr++) {
                float p0 = __expf(accs[nt][rr * 2 + 0]) * m0;
                float p1 = __expf(accs[nt][rr * 2 + 1]) * m1;
                if (rr == 0) den0 += p0 + p1; else den1 += p0 + p1;
                phf[nt >> 1][(nt & 1) * 2 + rr] = pack_f16x2(p0, p1);
            }
        }

        // ---- O += P @ V (fp16, 1 term)
        #pragma unroll
        for (int kt = 0; kt < 4; kt++) {
            #pragma unroll
            for (int np = 0; np < 4; np++) {
                uint32_t off = (uint32_t)(np * 16 * QSTR + kt * 32) + lboff;
                uint32_t vh4[4];
                ldsm4(vh4, vhu + off);
                mma_f16(accO[2*np],   phf[kt][0], phf[kt][1], phf[kt][2], phf[kt][3], vh4[0], vh4[1]);
                mma_f16(accO[2*np+1], phf[kt][0], phf[kt][1], phf[kt][2], phf[kt][3], vh4[2], vh4[3]);
            }
        }
        __syncthreads();
    }

    den0 += __shfl_xor_sync(0xffffffffu, den0, 1);
    den0 += __shfl_xor_sync(0xffffffffu, den0, 2);
    den1 += __shfl_xor_sync(0xffffffffu, den1, 1);
    den1 += __shfl_xor_sync(0xffffffffu, den1, 2);
    float inv0 = 1.f / (den0 + 1e-8f);
    float inv1 = 1.f / (den1 + 1e-8f);

    int q = bm + wq0 + fr;
    #pragma unroll
    for (int nt = 0; nt < 8; nt++) {
        int col = h * DK_ + nt * 8 + fc;
        float2 o0; o0.x = accO[nt][0] * inv0; o0.y = accO[nt][1] * inv0;
        float2 o1; o1.x = accO[nt][2] * inv1; o1.y = accO[nt][3] * inv1;
        *(float2*)&out[((size_t)(b * S_ + q)) * N_ + col] = o0;
        *(float2*)&out[((size_t)(b * S_ + q + 8)) * N_ + col] = o1;
    }
}

// ---------------------------------------------------------------------------
extern "C" void kernel_launch(void* const* d_in, const int* in_sizes, int n_in,
                              void* d_out, int out_size)
{
    const float* Q    = (const float*)d_in[0];
    const float* Kin  = (const float*)d_in[1];
    const float* Vin  = (const float*)d_in[2];
    const float* mask = (const float*)d_in[3];
    const float* Wq   = (const float*)d_in[4];
    const float* bq   = (const float*)d_in[5];
    const float* Wk   = (const float*)d_in[6];
    const float* bk   = (const float*)d_in[7];
    const float* Wv   = (const float*)d_in[8];
    const float* bv   = (const float*)d_in[9];
    float* out = (float*)d_out;

    __half *xhi, *whiT, *wloT;
    cudaGetSymbolAddress((void**)&xhi,  g_xhi);
    cudaGetSymbolAddress((void**)&whiT, g_wThi);
    cudaGetSymbolAddress((void**)&wloT, g_wTlo);

    const int psmem = 2 * STAGE_B;   // 61440
    cudaFuncSetAttribute(proj_all_kernel,
                         cudaFuncAttributeMaxDynamicSharedMemorySize, psmem);

    const int n4 = (M_ * KD_) / 4;
    split_all_kernel<<<dim3((n4 + 255) / 256, 3), 256>>>(
        (const float4*)Q, (const float4*)Kin, (const float4*)Vin,
        (uint2*)xhi, n4);
    splitT_all_kernel<<<dim3(N_ / 32, KD_ / 32, 3), dim3(32, 8)>>>(
        Wq, Wk, Wv, whiT, wloT);
    proj_all_kernel<<<dim3(N_ / 128, M_ / 128, 3), 256, psmem>>>(bq, bk, bv);

    const int asmem = OFFK + 2 * STG;   // 18432 + 37376 = 55808
    cudaFuncSetAttribute(attn_mma_kernel,
                         cudaFuncAttributeMaxDynamicSharedMemorySize, asmem);
    attn_mma_kernel<<<dim3(S_ / BR, B_ * H_), 256, asmem>>>(mask, out);
}

// round 14
// speedup vs baseline: 2.1490x; 1.1061x over previous
#include <cuda_runtime.h>
#include <cuda_fp16.h>
#include <cstdint>

#define B_  4
#define S_  2048
#define D_  1024
#define H_  16
#define DK_ 64
#define M_  (B_*S_)    // 8192
#define N_  (H_*DK_)   // 1024
#define KD_ D_         // 1024

// ---------------- device scratch (allocation-free rule: device globals) ----
__device__ __half g_xhi[3*M_*KD_];      // per z: Q,K,V inputs fp16
__device__ __half g_wThi[3*N_*KD_];     // per z: W transposed [n][k]
__device__ __half g_qh[B_*H_*S_*DK_];   // [bh][s][64]
__device__ __half g_kh[B_*H_*S_*DK_];
__device__ __half g_vth[B_*H_*DK_*S_];  // V^T: [bh][d][s]

// ---------------- helpers ---------------------------------------------------
__device__ __forceinline__ uint32_t smem_u32(const void* p) {
    uint32_t a;
    asm("{ .reg .u64 t; cvta.to.shared.u64 t, %1; cvt.u32.u64 %0, t; }"
        : "=r"(a) : "l"(p));
    return a;
}
__device__ __forceinline__ void cp16(void* dst, const void* src) {
    asm volatile("cp.async.cg.shared.global [%0], [%1], 16;"
                 :: "r"(smem_u32(dst)), "l"(src));
}
#define CP_COMMIT() asm volatile("cp.async.commit_group;" ::: "memory")
#define CP_WAIT1()  asm volatile("cp.async.wait_group 1;" ::: "memory")
#define CP_WAIT0()  asm volatile("cp.async.wait_group 0;" ::: "memory")

__device__ __forceinline__ void mma_f16(float* d,
                                        uint32_t a0, uint32_t a1, uint32_t a2, uint32_t a3,
                                        uint32_t b0, uint32_t b1)
{
    asm volatile(
        "mma.sync.aligned.m16n8k16.row.col.f32.f16.f16.f32 "
        "{%0,%1,%2,%3}, {%4,%5,%6,%7}, {%8,%9}, {%0,%1,%2,%3};"
        : "+f"(d[0]), "+f"(d[1]), "+f"(d[2]), "+f"(d[3])
        : "r"(a0), "r"(a1), "r"(a2), "r"(a3), "r"(b0), "r"(b1));
}
__device__ __forceinline__ void ldsm4(uint32_t* r, uint32_t addr) {
    asm volatile("ldmatrix.sync.aligned.m8n8.x4.shared.b16 {%0,%1,%2,%3}, [%4];"
                 : "=r"(r[0]), "=r"(r[1]), "=r"(r[2]), "=r"(r[3]) : "r"(addr));
}
__device__ __forceinline__ uint32_t pack_f16x2(float lo, float hi) {
    uint32_t r;
    asm("cvt.rn.f16x2.f32 %0, %1, %2;" : "=r"(r) : "f"(hi), "f"(lo));
    return r;
}

// ---------------- batched fp32 -> fp16 convert -------------------------------
__global__ void split_all_kernel(const float4* __restrict__ x0,
                                 const float4* __restrict__ x1,
                                 const float4* __restrict__ x2,
                                 uint2* __restrict__ hi, int n4)
{
    int i = blockIdx.x * blockDim.x + threadIdx.x;
    int z = blockIdx.y;
    if (i < n4) {
        const float4* x = (z == 0) ? x0 : (z == 1) ? x1 : x2;
        float4 v = x[i];
        uint2 h;
        h.x = pack_f16x2(v.x, v.y);
        h.y = pack_f16x2(v.z, v.w);
        hi[(size_t)z * n4 + i] = h;
    }
}

// batched W [K][N] -> transposed fp16 [N][K]; z = blockIdx.z
__global__ __launch_bounds__(256) void splitT_all_kernel(
    const float* __restrict__ w0, const float* __restrict__ w1,
    const float* __restrict__ w2,
    __half* __restrict__ hiT)
{
    __shared__ float t[32][33];
    const int tx = threadIdx.x;
    const int ty = threadIdx.y;
    const int k0 = blockIdx.y * 32;
    const int n0 = blockIdx.x * 32;
    const int z  = blockIdx.z;
    const float* w = (z == 0) ? w0 : (z == 1) ? w1 : w2;
    const size_t zo = (size_t)z * N_ * KD_;
    #pragma unroll
    for (int i = 0; i < 4; i++)
        t[ty + i * 8][tx] = w[(size_t)(k0 + ty + i * 8) * N_ + n0 + tx];
    __syncthreads();
    #pragma unroll
    for (int i = 0; i < 4; i++) {
        int n = n0 + ty + i * 8;
        int k = k0 + tx;
        hiT[zo + (size_t)n * KD_ + k] = __float2half(t[tx][ty + i * 8]);
    }
}

// ---------------- batched single-term fp16 projection GEMM ------------------
#define PAD      40
#define MAT_B    (128 * PAD * 2)
#define STAGE_B  (2 * MAT_B)
#define NKCH     (KD_ / 32)

__global__ __launch_bounds__(256, 3) void proj_all_kernel(
    const float* __restrict__ bq, const float* __restrict__ bk,
    const float* __restrict__ bv)
{
    extern __shared__ char psm[];

    const int tid  = threadIdx.x;
    const int wid  = tid >> 5;
    const int lane = tid & 31;
    const int wm   = wid >> 2;
    const int wn   = wid & 3;
    const int bm   = blockIdx.y * 128;
    const int bn   = blockIdx.x * 128;
    const int z    = blockIdx.z;

    const __half* xhi  = g_xhi  + (size_t)z * M_ * KD_;
    const __half* whiT = g_wThi + (size_t)z * N_ * KD_;
    const float* bias = (z == 0) ? bq : (z == 1) ? bk : bv;
    const float scale = (z == 0) ? 0.125f : 1.0f;

    float acc[4][4][4];
    #pragma unroll
    for (int i = 0; i < 4; i++)
        #pragma unroll
        for (int j = 0; j < 4; j++)
            #pragma unroll
            for (int r = 0; r < 4; r++) acc[i][j][r] = 0.f;

    // 2 matrices x 128 rows x 4 16B-units = 1024 units -> 4 iters x 256 thr
    auto load_stage = [&](int c, int s) {
        const int k0 = c * 32;
        char* st = psm + s * STAGE_B;
        #pragma unroll
        for (int t = 0; t < 4; t++) {
            int idx = tid + t * 256;
            int mat = idx >> 9;               // 0:aHi 1:bHi
            int rr  = (idx >> 2) & 127;
            int u   = idx & 3;
            const __half* src = (mat == 0) ? xhi : whiT;
            size_t off = (mat == 0)
                ? (size_t)(bm + rr) * KD_ + k0 + u * 8
                : (size_t)(bn + rr) * KD_ + k0 + u * 8;
            cp16(st + mat * MAT_B + rr * (PAD * 2) + u * 16, src + off);
        }
        CP_COMMIT();
    };

    const int fr   = lane >> 2;
    const int fc   = (lane & 3) * 2;
    const int lrow = lane & 7;
    const int lm   = lane >> 3;
    const uint32_t psm_u = smem_u32(psm);

    auto compute = [&](int s) {
        const uint32_t aHi = psm_u + s * STAGE_B;
        const uint32_t bHi = aHi + MAT_B;
        #pragma unroll
        for (int ks = 0; ks < 2; ks++) {
            const int kc = ks * 16;
            const uint32_t aoff = (uint32_t)(((lm & 1) * 8 + lrow) * (PAD * 2)
                                             + (kc + (lm >> 1) * 8) * 2);
            const uint32_t boff = (uint32_t)(((lm >> 1) * 8 + lrow) * (PAD * 2)
                                             + (kc + (lm & 1) * 8) * 2);
            uint32_t af[4][4], bh[8];
            #pragma unroll
            for (int i = 0; i < 4; i++) {
                uint32_t ra = (uint32_t)((wm * 64 + i * 16) * (PAD * 2));
                ldsm4(af[i], aHi + ra + aoff);
            }
            #pragma unroll
            for (int jb = 0; jb < 2; jb++) {
                uint32_t rb = (uint32_t)((wn * 32 + jb * 16) * (PAD * 2));
                ldsm4(&bh[jb * 4], bHi + rb + boff);
            }
            #pragma unroll
            for (int i = 0; i < 4; i++)
                #pragma unroll
                for (int j = 0; j < 4; j++)
                    mma_f16(acc[i][j], af[i][0], af[i][1], af[i][2], af[i][3],
                            bh[j * 2], bh[j * 2 + 1]);
        }
    };

    load_stage(0, 0);
    for (int c = 0; c < NKCH; c++) {
        const int s = c & 1;
        if (c + 1 < NKCH) load_stage(c + 1, s ^ 1);
        if (c + 1 < NKCH) { CP_WAIT1(); } else { CP_WAIT0(); }
        __syncthreads();
        compute(s);
        __syncthreads();
    }

    // epilogue: bias+scale, round to fp16, write (V transposed when z==2)
    #pragma unroll
    for (int i = 0; i < 4; i++) {
        #pragma unroll
        for (int rr = 0; rr < 2; rr++) {
            int m = bm + wm * 64 + i * 16 + fr + rr * 8;
            int b = m >> 11;
            int sdx = m & (S_ - 1);
            #pragma unroll
            for (int j = 0; j < 4; j++) {
                int n0 = bn + wn * 32 + j * 8 + fc;
                int h  = n0 >> 6;
                int d  = n0 & 63;
                float x0 = (acc[i][j][rr * 2 + 0] + bias[n0 + 0]) * scale;
                float x1 = (acc[i][j][rr * 2 + 1] + bias[n0 + 1]) * scale;
                __half h0 = __float2half(x0);
                __half h1 = __float2half(x1);
                if (z == 0) {
                    size_t o = (((size_t)(b * H_ + h) * S_) + sdx) * DK_ + d;
                    __half2 ph; ph.x = h0; ph.y = h1;
                    *(__half2*)&g_qh[o] = ph;
                } else if (z == 1) {
                    size_t o = (((size_t)(b * H_ + h) * S_) + sdx) * DK_ + d;
                    __half2 ph; ph.x = h0; ph.y = h1;
                    *(__half2*)&g_kh[o] = ph;
                } else {
                    size_t o = ((size_t)(b * H_ + h) * DK_ + d) * S_ + sdx;
                    g_vth[o] = h0; g_vth[o + S_] = h1;
                }
            }
        }
    }
}

// ---------------- tensor-core attention (pure fp16, BR=128) -----------------
#define BR   128
#define KC   64
#define NCHA (S_ / KC)     // 32
#define QSTR 144           // bytes/row (72 halves)
#define KMAT (64 * QSTR)   // 9216
#define STG  (2 * KMAT + 256)      // 18688 (kh + vh + mask)
#define OFFK (BR * QSTR)           // 18432 (after qh)

__global__ __launch_bounds__(256, 2) void attn_mma_kernel(
    const float* __restrict__ maskg, float* __restrict__ out)
{
    extern __shared__ char smc[];

    const int tid  = threadIdx.x;
    const int wid  = tid >> 5;
    const int lane = tid & 31;
    const int fr   = lane >> 2;
    const int fc   = (lane & 3) * 2;
    const int lrow = lane & 7;
    const int lm   = lane >> 3;
    const int bh   = blockIdx.y;
    const int b    = bh >> 4;
    const int h    = bh & 15;
    const int bm   = blockIdx.x * BR;
    const int wq0  = wid * 16;

    const __half* qh_g = g_qh + ((size_t)bh * S_ + bm) * DK_;

    // Q load (joins chunk 0's commit group): 1024 16B units
    #pragma unroll
    for (int t = 0; t < 4; t++) {
        int idx = tid + t * 256;
        int r = idx >> 3, u = idx & 7;
        cp16(smc + r * QSTR + u * 16, qh_g + r * DK_ + u * 8);
    }

    auto load_chunk = [&](int c, int s) {
        const int k0 = c * KC;
        char* st = smc + OFFK + s * STG;
        #pragma unroll
        for (int t = 0; t < 2; t++) {
            int idx = tid + t * 256;      // 0..511 : 64 rows x 8 units
            int r = idx >> 3, u = idx & 7;
            cp16(st + r * QSTR + u * 16,
                 g_kh + ((size_t)bh * S_ + k0 + r) * DK_ + u * 8);
            cp16(st + KMAT + r * QSTR + u * 16,
                 g_vth + ((size_t)bh * DK_ + r) * S_ + k0 + u * 8);
        }
        if (tid < 16) cp16(st + 2 * KMAT + tid * 16, maskg + (size_t)b * S_ + k0 + tid * 4);
        CP_COMMIT();
    };

    load_chunk(0, 0);

    uint32_t qf[4][4];
    float accO[8][4];
    #pragma unroll
    for (int n = 0; n < 8; n++)
        #pragma unroll
        for (int r = 0; r < 4; r++) accO[n][r] = 0.f;
    float den0 = 0.f, den1 = 0.f;

    const uint32_t smc_u = smem_u32(smc);
    const uint32_t lboff = (uint32_t)(((lm >> 1) * 8 + lrow) * QSTR + (lm & 1) * 16);

    for (int c = 0; c < NCHA; c++) {
        const int s = c & 1;
        if (c + 1 < NCHA) load_chunk(c + 1, s ^ 1);
        if (c + 1 < NCHA) { CP_WAIT1(); } else { CP_WAIT0(); }
        __syncthreads();

        if (c == 0) {
            const char* qhB = smc;
            int r0 = wq0 + fr;
            #pragma unroll
            for (int kt = 0; kt < 4; kt++) {
                int cb = (kt * 16 + fc) * 2;
                qf[kt][0] = *(const uint32_t*)(qhB + r0 * QSTR + cb);
                qf[kt][1] = *(const uint32_t*)(qhB + (r0 + 8) * QSTR + cb);
                qf[kt][2] = *(const uint32_t*)(qhB + r0 * QSTR + cb + 16);
                qf[kt][3] = *(const uint32_t*)(qhB + (r0 + 8) * QSTR + cb + 16);
            }
        }

        const uint32_t khu = smc_u + OFFK + (uint32_t)(s * STG);
        const uint32_t vhu = khu + KMAT;
        const float* mk = (const float*)(smc + OFFK + s * STG + 2 * KMAT);

        // ---- scores (fp16, 1 term)
        float accs[8][4];
        #pragma unroll
        for (int n = 0; n < 8; n++)
            #pragma unroll
            for (int r = 0; r < 4; r++) accs[n][r] = 0.f;

        #pragma unroll
        for (int kt = 0; kt < 4; kt++) {
            #pragma unroll
            for (int np = 0; np < 4; np++) {
                uint32_t off = (uint32_t)(np * 16 * QSTR + kt * 32) + lboff;
                uint32_t bh4[4];
                ldsm4(bh4, khu + off);
                mma_f16(accs[2*np],   qf[kt][0], qf[kt][1], qf[kt][2], qf[kt][3], bh4[0], bh4[1]);
                mma_f16(accs[2*np+1], qf[kt][0], qf[kt][1], qf[kt][2], qf[kt][3], bh4[2], bh4[3]);
            }
        }

        // ---- P = exp(s) * mask; fp16 pack; denom (fp32, pre-rounding)
        uint32_t phf[4][4];
        #pragma unroll
        for (int nt = 0; nt < 8; nt++) {
            float m0 = mk[nt * 8 + fc];
            float m1 = mk[nt * 8 + fc + 1];
            #pragma unroll
            for (int rr = 0; rr < 2; rr++) {
                float p0 = __expf(accs[nt][rr * 2 + 0]) * m0;
                float p1 = __expf(accs[nt][rr * 2 + 1]) * m1;
                if (rr == 0) den0 += p0 + p1; else den1 += p0 + p1;
                phf[nt >> 1][(nt & 1) * 2 + rr] = pack_f16x2(p0, p1);
            }
        }

        // ---- O += P @ V (fp16, 1 term)
        #pragma unroll
        for (int kt = 0; kt < 4; kt++) {
            #pragma unroll
            for (int np = 0; np < 4; np++) {
                uint32_t off = (uint32_t)(np * 16 * QSTR + kt * 32) + lboff;
                uint32_t vh4[4];
                ldsm4(vh4, vhu + off);
                mma_f16(accO[2*np],   phf[kt][0], phf[kt][1], phf[kt][2], phf[kt][3], vh4[0], vh4[1]);
                mma_f16(accO[2*np+1], phf[kt][0], phf[kt][1], phf[kt][2], phf[kt][3], vh4[2], vh4[3]);
            }
        }
        __syncthreads();
    }

    den0 += __shfl_xor_sync(0xffffffffu, den0, 1);
    den0 += __shfl_xor_sync(0xffffffffu, den0, 2);
    den1 += __shfl_xor_sync(0xffffffffu, den1, 1);
    den1 += __shfl_xor_sync(0xffffffffu, den1, 2);
    float inv0 = 1.f / (den0 + 1e-8f);
    float inv1 = 1.f / (den1 + 1e-8f);

    int q = bm + wq0 + fr;
    #pragma unroll
    for (int nt = 0; nt < 8; nt++) {
        int col = h * DK_ + nt * 8 + fc;
        float2 o0; o0.x = accO[nt][0] * inv0; o0.y = accO[nt][1] * inv0;
        float2 o1; o1.x = accO[nt][2] * inv1; o1.y = accO[nt][3] * inv1;
        *(float2*)&out[((size_t)(b * S_ + q)) * N_ + col] = o0;
        *(float2*)&out[((size_t)(b * S_ + q + 8)) * N_ + col] = o1;
    }
}

// ---------------------------------------------------------------------------
extern "C" void kernel_launch(void* const* d_in, const int* in_sizes, int n_in,
                              void* d_out, int out_size)
{
    const float* Q    = (const float*)d_in[0];
    const float* Kin  = (const float*)d_in[1];
    const float* Vin  = (const float*)d_in[2];
    const float* mask = (const float*)d_in[3];
    const float* Wq   = (const float*)d_in[4];
    const float* bq   = (const float*)d_in[5];
    const float* Wk   = (const float*)d_in[6];
    const float* bk   = (const float*)d_in[7];
    const float* Wv   = (const float*)d_in[8];
    const float* bv   = (const float*)d_in[9];
    float* out = (float*)d_out;

    __half *xhi, *whiT;
    cudaGetSymbolAddress((void**)&xhi,  g_xhi);
    cudaGetSymbolAddress((void**)&whiT, g_wThi);

    const int psmem = 2 * STAGE_B;   // 40960
    cudaFuncSetAttribute(proj_all_kernel,
                         cudaFuncAttributeMaxDynamicSharedMemorySize, psmem);

    const int n4 = (M_ * KD_) / 4;
    split_all_kernel<<<dim3((n4 + 255) / 256, 3), 256>>>(
        (const float4*)Q, (const float4*)Kin, (const float4*)Vin,
        (uint2*)xhi, n4);
    splitT_all_kernel<<<dim3(N_ / 32, KD_ / 32, 3), dim3(32, 8)>>>(
        Wq, Wk, Wv, whiT);
    proj_all_kernel<<<dim3(N_ / 128, M_ / 128, 3), 256, psmem>>>(bq, bk, bv);

    const int asmem = OFFK + 2 * STG;   // 18432 + 37376 = 55808
    cudaFuncSetAttribute(attn_mma_kernel,
                         cudaFuncAttributeMaxDynamicSharedMemorySize, asmem);
    attn_mma_kernel<<<dim3(S_ / BR, B_ * H_), 256, asmem>>>(mask, out);
}

// round 15
// speedup vs baseline: 2.6581x; 1.2369x over previous
#include <cuda_runtime.h>
#include <cuda_fp16.h>
#include <cstdint>

#define B_  4
#define S_  2048
#define D_  1024
#define H_  16
#define DK_ 64
#define M_  (B_*S_)    // 8192
#define N_  (H_*DK_)   // 1024
#define KD_ D_         // 1024

// ---------------- device scratch (allocation-free rule: device globals) ----
__device__ __half g_xhi[3*M_*KD_];      // per z: Q,K,V inputs fp16
__device__ __half g_wThi[3*N_*KD_];     // per z: W transposed [n][k]
__device__ __half g_qh[B_*H_*S_*DK_];   // [bh][s][64]
__device__ __half g_kh[B_*H_*S_*DK_];
__device__ __half g_vth[B_*H_*DK_*S_];  // V^T: [bh][d][s]

// ---------------- helpers ---------------------------------------------------
__device__ __forceinline__ uint32_t smem_u32(const void* p) {
    uint32_t a;
    asm("{ .reg .u64 t; cvta.to.shared.u64 t, %1; cvt.u32.u64 %0, t; }"
        : "=r"(a) : "l"(p));
    return a;
}
__device__ __forceinline__ void cp16(void* dst, const void* src) {
    asm volatile("cp.async.cg.shared.global [%0], [%1], 16;"
                 :: "r"(smem_u32(dst)), "l"(src));
}
#define CP_COMMIT() asm volatile("cp.async.commit_group;" ::: "memory")
#define CP_WAIT1()  asm volatile("cp.async.wait_group 1;" ::: "memory")
#define CP_WAIT0()  asm volatile("cp.async.wait_group 0;" ::: "memory")

__device__ __forceinline__ void mma_f16(float* d,
                                        uint32_t a0, uint32_t a1, uint32_t a2, uint32_t a3,
                                        uint32_t b0, uint32_t b1)
{
    asm volatile(
        "mma.sync.aligned.m16n8k16.row.col.f32.f16.f16.f32 "
        "{%0,%1,%2,%3}, {%4,%5,%6,%7}, {%8,%9}, {%0,%1,%2,%3};"
        : "+f"(d[0]), "+f"(d[1]), "+f"(d[2]), "+f"(d[3])
        : "r"(a0), "r"(a1), "r"(a2), "r"(a3), "r"(b0), "r"(b1));
}
__device__ __forceinline__ void ldsm4(uint32_t* r, uint32_t addr) {
    asm volatile("ldmatrix.sync.aligned.m8n8.x4.shared.b16 {%0,%1,%2,%3}, [%4];"
                 : "=r"(r[0]), "=r"(r[1]), "=r"(r[2]), "=r"(r[3]) : "r"(addr));
}
__device__ __forceinline__ uint32_t pack_f16x2(float lo, float hi) {
    uint32_t r;
    asm("cvt.rn.f16x2.f32 %0, %1, %2;" : "=r"(r) : "f"(hi), "f"(lo));
    return r;
}

// ---------------- batched fp32 -> fp16 convert -------------------------------
__global__ void split_all_kernel(const float4* __restrict__ x0,
                                 const float4* __restrict__ x1,
                                 const float4* __restrict__ x2,
                                 uint2* __restrict__ hi, int n4)
{
    int i = blockIdx.x * blockDim.x + threadIdx.x;
    int z = blockIdx.y;
    if (i < n4) {
        const float4* x = (z == 0) ? x0 : (z == 1) ? x1 : x2;
        float4 v = x[i];
        uint2 h;
        h.x = pack_f16x2(v.x, v.y);
        h.y = pack_f16x2(v.z, v.w);
        hi[(size_t)z * n4 + i] = h;
    }
}

// batched W [K][N] -> transposed fp16 [N][K]; z = blockIdx.z
__global__ __launch_bounds__(256) void splitT_all_kernel(
    const float* __restrict__ w0, const float* __restrict__ w1,
    const float* __restrict__ w2,
    __half* __restrict__ hiT)
{
    __shared__ float t[32][33];
    const int tx = threadIdx.x;
    const int ty = threadIdx.y;
    const int k0 = blockIdx.y * 32;
    const int n0 = blockIdx.x * 32;
    const int z  = blockIdx.z;
    const float* w = (z == 0) ? w0 : (z == 1) ? w1 : w2;
    const size_t zo = (size_t)z * N_ * KD_;
    #pragma unroll
    for (int i = 0; i < 4; i++)
        t[ty + i * 8][tx] = w[(size_t)(k0 + ty + i * 8) * N_ + n0 + tx];
    __syncthreads();
    #pragma unroll
    for (int i = 0; i < 4; i++) {
        int n = n0 + ty + i * 8;
        int k = k0 + tx;
        hiT[zo + (size_t)n * KD_ + k] = __float2half(t[tx][ty + i * 8]);
    }
}

// ---------------- batched single-term fp16 projection GEMM ------------------
// 3-stage cp.async ring, ONE barrier per chunk.
#define PAD      40
#define MAT_B    (128 * PAD * 2)
#define STAGE_B  (2 * MAT_B)
#define NKCH     (KD_ / 32)

__global__ __launch_bounds__(256, 2) void proj_all_kernel(
    const float* __restrict__ bq, const float* __restrict__ bk,
    const float* __restrict__ bv)
{
    extern __shared__ char psm[];

    const int tid  = threadIdx.x;
    const int wid  = tid >> 5;
    const int lane = tid & 31;
    const int wm   = wid >> 2;
    const int wn   = wid & 3;
    const int bm   = blockIdx.y * 128;
    const int bn   = blockIdx.x * 128;
    const int z    = blockIdx.z;

    const __half* xhi  = g_xhi  + (size_t)z * M_ * KD_;
    const __half* whiT = g_wThi + (size_t)z * N_ * KD_;
    const float* bias = (z == 0) ? bq : (z == 1) ? bk : bv;
    const float scale = (z == 0) ? 0.125f : 1.0f;

    float acc[4][4][4];
    #pragma unroll
    for (int i = 0; i < 4; i++)
        #pragma unroll
        for (int j = 0; j < 4; j++)
            #pragma unroll
            for (int r = 0; r < 4; r++) acc[i][j][r] = 0.f;

    auto load_stage = [&](int c, int s) {
        const int k0 = c * 32;
        char* st = psm + s * STAGE_B;
        #pragma unroll
        for (int t = 0; t < 4; t++) {
            int idx = tid + t * 256;
            int mat = idx >> 9;               // 0:aHi 1:bHi
            int rr  = (idx >> 2) & 127;
            int u   = idx & 3;
            const __half* src = (mat == 0) ? xhi : whiT;
            size_t off = (mat == 0)
                ? (size_t)(bm + rr) * KD_ + k0 + u * 8
                : (size_t)(bn + rr) * KD_ + k0 + u * 8;
            cp16(st + mat * MAT_B + rr * (PAD * 2) + u * 16, src + off);
        }
        CP_COMMIT();
    };

    const int fr   = lane >> 2;
    const int fc   = (lane & 3) * 2;
    const int lrow = lane & 7;
    const int lm   = lane >> 3;
    const uint32_t psm_u = smem_u32(psm);

    auto compute = [&](int s) {
        const uint32_t aHi = psm_u + s * STAGE_B;
        const uint32_t bHi = aHi + MAT_B;
        #pragma unroll
        for (int ks = 0; ks < 2; ks++) {
            const int kc = ks * 16;
            const uint32_t aoff = (uint32_t)(((lm & 1) * 8 + lrow) * (PAD * 2)
                                             + (kc + (lm >> 1) * 8) * 2);
            const uint32_t boff = (uint32_t)(((lm >> 1) * 8 + lrow) * (PAD * 2)
                                             + (kc + (lm & 1) * 8) * 2);
            uint32_t af[4][4], bh[8];
            #pragma unroll
            for (int i = 0; i < 4; i++) {
                uint32_t ra = (uint32_t)((wm * 64 + i * 16) * (PAD * 2));
                ldsm4(af[i], aHi + ra + aoff);
            }
            #pragma unroll
            for (int jb = 0; jb < 2; jb++) {
                uint32_t rb = (uint32_t)((wn * 32 + jb * 16) * (PAD * 2));
                ldsm4(&bh[jb * 4], bHi + rb + boff);
            }
            #pragma unroll
            for (int i = 0; i < 4; i++)
                #pragma unroll
                for (int j = 0; j < 4; j++)
                    mma_f16(acc[i][j], af[i][0], af[i][1], af[i][2], af[i][3],
                            bh[j * 2], bh[j * 2 + 1]);
        }
    };

    load_stage(0, 0);
    load_stage(1, 1);
    for (int c = 0; c < NKCH; c++) {
        if (c + 1 < NKCH) { CP_WAIT1(); } else { CP_WAIT0(); }
        __syncthreads();                       // all warps done with stage (c+2)%3
        compute(c % 3);
        if (c + 2 < NKCH) load_stage(c + 2, (c + 2) % 3);
    }

    // epilogue: bias+scale, round to fp16, write (V transposed when z==2)
    #pragma unroll
    for (int i = 0; i < 4; i++) {
        #pragma unroll
        for (int rr = 0; rr < 2; rr++) {
            int m = bm + wm * 64 + i * 16 + fr + rr * 8;
            int b = m >> 11;
            int sdx = m & (S_ - 1);
            #pragma unroll
            for (int j = 0; j < 4; j++) {
                int n0 = bn + wn * 32 + j * 8 + fc;
                int h  = n0 >> 6;
                int d  = n0 & 63;
                float x0 = (acc[i][j][rr * 2 + 0] + bias[n0 + 0]) * scale;
                float x1 = (acc[i][j][rr * 2 + 1] + bias[n0 + 1]) * scale;
                __half h0 = __float2half(x0);
                __half h1 = __float2half(x1);
                if (z == 0) {
                    size_t o = (((size_t)(b * H_ + h) * S_) + sdx) * DK_ + d;
                    __half2 ph; ph.x = h0; ph.y = h1;
                    *(__half2*)&g_qh[o] = ph;
                } else if (z == 1) {
                    size_t o = (((size_t)(b * H_ + h) * S_) + sdx) * DK_ + d;
                    __half2 ph; ph.x = h0; ph.y = h1;
                    *(__half2*)&g_kh[o] = ph;
                } else {
                    size_t o = ((size_t)(b * H_ + h) * DK_ + d) * S_ + sdx;
                    g_vth[o] = h0; g_vth[o + S_] = h1;
                }
            }
        }
    }
}

// ---------------- tensor-core attention (pure fp16, BR=128, 3-stage ring) ---
#define BR   128
#define KC   64
#define NCHA (S_ / KC)     // 32
#define QSTR 144           // bytes/row (72 halves)
#define KMAT (64 * QSTR)   // 9216
#define STG  (2 * KMAT + 256)      // 18688 (kh + vh + mask)
#define OFFK (BR * QSTR)           // 18432 (after qh)

__global__ __launch_bounds__(256, 2) void attn_mma_kernel(
    const float* __restrict__ maskg, float* __restrict__ out)
{
    extern __shared__ char smc[];

    const int tid  = threadIdx.x;
    const int wid  = tid >> 5;
    const int lane = tid & 31;
    const int fr   = lane >> 2;
    const int fc   = (lane & 3) * 2;
    const int lrow = lane & 7;
    const int lm   = lane >> 3;
    const int bh   = blockIdx.y;
    const int b    = bh >> 4;
    const int h    = bh & 15;
    const int bm   = blockIdx.x * BR;
    const int wq0  = wid * 16;

    const __half* qh_g = g_qh + ((size_t)bh * S_ + bm) * DK_;

    // Q load (joins chunk 0's commit group): 1024 16B units
    #pragma unroll
    for (int t = 0; t < 4; t++) {
        int idx = tid + t * 256;
        int r = idx >> 3, u = idx & 7;
        cp16(smc + r * QSTR + u * 16, qh_g + r * DK_ + u * 8);
    }

    auto load_chunk = [&](int c, int s) {
        const int k0 = c * KC;
        char* st = smc + OFFK + s * STG;
        #pragma unroll
        for (int t = 0; t < 2; t++) {
            int idx = tid + t * 256;      // 0..511 : 64 rows x 8 units
            int r = idx >> 3, u = idx & 7;
            cp16(st + r * QSTR + u * 16,
                 g_kh + ((size_t)bh * S_ + k0 + r) * DK_ + u * 8);
            cp16(st + KMAT + r * QSTR + u * 16,
                 g_vth + ((size_t)bh * DK_ + r) * S_ + k0 + u * 8);
        }
        if (tid < 16) cp16(st + 2 * KMAT + tid * 16, maskg + (size_t)b * S_ + k0 + tid * 4);
        CP_COMMIT();
    };

    load_chunk(0, 0);
    load_chunk(1, 1);

    uint32_t qf[4][4];
    float accO[8][4];
    #pragma unroll
    for (int n = 0; n < 8; n++)
        #pragma unroll
        for (int r = 0; r < 4; r++) accO[n][r] = 0.f;
    float den0 = 0.f, den1 = 0.f;

    const uint32_t smc_u = smem_u32(smc);
    const uint32_t lboff = (uint32_t)(((lm >> 1) * 8 + lrow) * QSTR + (lm & 1) * 16);

    for (int c = 0; c < NCHA; c++) {
        const int s = c % 3;
        if (c + 1 < NCHA) { CP_WAIT1(); } else { CP_WAIT0(); }
        __syncthreads();                       // all warps done with stage (c+2)%3

        if (c == 0) {
            const char* qhB = smc;
            int r0 = wq0 + fr;
            #pragma unroll
            for (int kt = 0; kt < 4; kt++) {
                int cb = (kt * 16 + fc) * 2;
                qf[kt][0] = *(const uint32_t*)(qhB + r0 * QSTR + cb);
                qf[kt][1] = *(const uint32_t*)(qhB + (r0 + 8) * QSTR + cb);
                qf[kt][2] = *(const uint32_t*)(qhB + r0 * QSTR + cb + 16);
                qf[kt][3] = *(const uint32_t*)(qhB + (r0 + 8) * QSTR + cb + 16);
            }
        }

        const uint32_t khu = smc_u + OFFK + (uint32_t)(s * STG);
        const uint32_t vhu = khu + KMAT;
        const float* mk = (const float*)(smc + OFFK + s * STG + 2 * KMAT);

        // ---- scores (fp16, 1 term)
        float accs[8][4];
        #pragma unroll
        for (int n = 0; n < 8; n++)
            #pragma unroll
            for (int r = 0; r < 4; r++) accs[n][r] = 0.f;

        #pragma unroll
        for (int kt = 0; kt < 4; kt++) {
            #pragma unroll
            for (int np = 0; np < 4; np++) {
                uint32_t off = (uint32_t)(np * 16 * QSTR + kt * 32) + lboff;
                uint32_t bh4[4];
                ldsm4(bh4, khu + off);
                mma_f16(accs[2*np],   qf[kt][0], qf[kt][1], qf[kt][2], qf[kt][3], bh4[0], bh4[1]);
                mma_f16(accs[2*np+1], qf[kt][0], qf[kt][1], qf[kt][2], qf[kt][3], bh4[2], bh4[3]);
            }
        }

        // ---- P = exp(s) * mask; fp16 pack; denom (fp32, pre-rounding)
        uint32_t phf[4][4];
        #pragma unroll
        for (int nt = 0; nt < 8; nt++) {
            float m0 = mk[nt * 8 + fc];
            float m1 = mk[nt * 8 + fc + 1];
            #pragma unroll
            for (int rr = 0; rr < 2; rr++) {
                float p0 = __expf(accs[nt][rr * 2 + 0]) * m0;
                float p1 = __expf(accs[nt][rr * 2 + 1]) * m1;
                if (rr == 0) den0 += p0 + p1; else den1 += p0 + p1;
                phf[nt >> 1][(nt & 1) * 2 + rr] = pack_f16x2(p0, p1);
            }
        }

        // ---- O += P @ V (fp16, 1 term)
        #pragma unroll
        for (int kt = 0; kt < 4; kt++) {
            #pragma unroll
            for (int np = 0; np < 4; np++) {
                uint32_t off = (uint32_t)(np * 16 * QSTR + kt * 32) + lboff;
                uint32_t vh4[4];
                ldsm4(vh4, vhu + off);
                mma_f16(accO[2*np],   phf[kt][0], phf[kt][1], phf[kt][2], phf[kt][3], vh4[0], vh4[1]);
                mma_f16(accO[2*np+1], phf[kt][0], phf[kt][1], phf[kt][2], phf[kt][3], vh4[2], vh4[3]);
            }
        }

        if (c + 2 < NCHA) load_chunk(c + 2, (c + 2) % 3);
    }

    den0 += __shfl_xor_sync(0xffffffffu, den0, 1);
    den0 += __shfl_xor_sync(0xffffffffu, den0, 2);
    den1 += __shfl_xor_sync(0xffffffffu, den1, 1);
    den1 += __shfl_xor_sync(0xffffffffu, den1, 2);
    float inv0 = 1.f / (den0 + 1e-8f);
    float inv1 = 1.f / (den1 + 1e-8f);

    int q = bm + wq0 + fr;
    #pragma unroll
    for (int nt = 0; nt < 8; nt++) {
        int col = h * DK_ + nt * 8 + fc;
        float2 o0; o0.x = accO[nt][0] * inv0; o0.y = accO[nt][1] * inv0;
        float2 o1; o1.x = accO[nt][2] * inv1; o1.y = accO[nt][3] * inv1;
        *(float2*)&out[((size_t)(b * S_ + q)) * N_ + col] = o0;
        *(float2*)&out[((size_t)(b * S_ + q + 8)) * N_ + col] = o1;
    }
}

// ---------------------------------------------------------------------------
extern "C" void kernel_launch(void* const* d_in, const int* in_sizes, int n_in,
                              void* d_out, int out_size)
{
    const float* Q    = (const float*)d_in[0];
    const float* Kin  = (const float*)d_in[1];
    const float* Vin  = (const float*)d_in[2];
    const float* mask = (const float*)d_in[3];
    const float* Wq   = (const float*)d_in[4];
    const float* bq   = (const float*)d_in[5];
    const float* Wk   = (const float*)d_in[6];
    const float* bk   = (const float*)d_in[7];
    const float* Wv   = (const float*)d_in[8];
    const float* bv   = (const float*)d_in[9];
    float* out = (float*)d_out;

    __half *xhi, *whiT;
    cudaGetSymbolAddress((void**)&xhi,  g_xhi);
    cudaGetSymbolAddress((void**)&whiT, g_wThi);

    const int psmem = 3 * STAGE_B;   // 61440
    cudaFuncSetAttribute(proj_all_kernel,
                         cudaFuncAttributeMaxDynamicSharedMemorySize, psmem);

    const int n4 = (M_ * KD_) / 4;
    split_all_kernel<<<dim3((n4 + 255) / 256, 3), 256>>>(
        (const float4*)Q, (const float4*)Kin, (const float4*)Vin,
        (uint2*)xhi, n4);
    splitT_all_kernel<<<dim3(N_ / 32, KD_ / 32, 3), dim3(32, 8)>>>(
        Wq, Wk, Wv, whiT);
    proj_all_kernel<<<dim3(N_ / 128, M_ / 128, 3), 256, psmem>>>(bq, bk, bv);

    const int asmem = OFFK + 3 * STG;   // 18432 + 56064 = 74496
    cudaFuncSetAttribute(attn_mma_kernel,
                         cudaFuncAttributeMaxDynamicSharedMemorySize, asmem);
    attn_mma_kernel<<<dim3(S_ / BR, B_ * H_), 256, asmem>>>(mask, out);
}

// round 16
// speedup vs baseline: 2.6894x; 1.0118x over previous
#include <cuda_runtime.h>
#include <cuda_fp16.h>
#include <cstdint>

#define B_  4
#define S_  2048
#define D_  1024
#define H_  16
#define DK_ 64
#define M_  (B_*S_)    // 8192
#define N_  (H_*DK_)   // 1024
#define KD_ D_         // 1024

// ---------------- device scratch (allocation-free rule: device globals) ----
__device__ __half g_xhi[3*M_*KD_];      // per z: Q,K,V inputs fp16
__device__ __half g_wThi[3*N_*KD_];     // per z: W transposed [n][k]
__device__ __half g_qh[B_*H_*S_*DK_];   // [bh][s][64]
__device__ __half g_kh[B_*H_*S_*DK_];
__device__ __half g_vth[B_*H_*DK_*S_];  // V^T: [bh][d][s]

// ---------------- helpers ---------------------------------------------------
__device__ __forceinline__ uint32_t smem_u32(const void* p) {
    uint32_t a;
    asm("{ .reg .u64 t; cvta.to.shared.u64 t, %1; cvt.u32.u64 %0, t; }"
        : "=r"(a) : "l"(p));
    return a;
}
__device__ __forceinline__ void cp16(void* dst, const void* src) {
    asm volatile("cp.async.cg.shared.global [%0], [%1], 16;"
                 :: "r"(smem_u32(dst)), "l"(src));
}
#define CP_COMMIT() asm volatile("cp.async.commit_group;" ::: "memory")
#define CP_WAIT1()  asm volatile("cp.async.wait_group 1;" ::: "memory")
#define CP_WAIT0()  asm volatile("cp.async.wait_group 0;" ::: "memory")

__device__ __forceinline__ void mma_f16(float* d,
                                        uint32_t a0, uint32_t a1, uint32_t a2, uint32_t a3,
                                        uint32_t b0, uint32_t b1)
{
    asm volatile(
        "mma.sync.aligned.m16n8k16.row.col.f32.f16.f16.f32 "
        "{%0,%1,%2,%3}, {%4,%5,%6,%7}, {%8,%9}, {%0,%1,%2,%3};"
        : "+f"(d[0]), "+f"(d[1]), "+f"(d[2]), "+f"(d[3])
        : "r"(a0), "r"(a1), "r"(a2), "r"(a3), "r"(b0), "r"(b1));
}
__device__ __forceinline__ void ldsm4(uint32_t* r, uint32_t addr) {
    asm volatile("ldmatrix.sync.aligned.m8n8.x4.shared.b16 {%0,%1,%2,%3}, [%4];"
                 : "=r"(r[0]), "=r"(r[1]), "=r"(r[2]), "=r"(r[3]) : "r"(addr));
}
__device__ __forceinline__ uint32_t pack_f16x2(float lo, float hi) {
    uint32_t r;
    asm("cvt.rn.f16x2.f32 %0, %1, %2;" : "=r"(r) : "f"(hi), "f"(lo));
    return r;
}

// ---------------- batched fp32 -> fp16 convert -------------------------------
__global__ void split_all_kernel(const float4* __restrict__ x0,
                                 const float4* __restrict__ x1,
                                 const float4* __restrict__ x2,
                                 uint2* __restrict__ hi, int n4)
{
    int i = blockIdx.x * blockDim.x + threadIdx.x;
    int z = blockIdx.y;
    if (i < n4) {
        const float4* x = (z == 0) ? x0 : (z == 1) ? x1 : x2;
        float4 v = x[i];
        uint2 h;
        h.x = pack_f16x2(v.x, v.y);
        h.y = pack_f16x2(v.z, v.w);
        hi[(size_t)z * n4 + i] = h;
    }
}

// batched W [K][N] -> transposed fp16 [N][K]; z = blockIdx.z
__global__ __launch_bounds__(256) void splitT_all_kernel(
    const float* __restrict__ w0, const float* __restrict__ w1,
    const float* __restrict__ w2,
    __half* __restrict__ hiT)
{
    __shared__ float t[32][33];
    const int tx = threadIdx.x;
    const int ty = threadIdx.y;
    const int k0 = blockIdx.y * 32;
    const int n0 = blockIdx.x * 32;
    const int z  = blockIdx.z;
    const float* w = (z == 0) ? w0 : (z == 1) ? w1 : w2;
    const size_t zo = (size_t)z * N_ * KD_;
    #pragma unroll
    for (int i = 0; i < 4; i++)
        t[ty + i * 8][tx] = w[(size_t)(k0 + ty + i * 8) * N_ + n0 + tx];
    __syncthreads();
    #pragma unroll
    for (int i = 0; i < 4; i++) {
        int n = n0 + ty + i * 8;
        int k = k0 + tx;
        hiT[zo + (size_t)n * KD_ + k] = __float2half(t[tx][ty + i * 8]);
    }
}

// ---------------- batched single-term fp16 projection GEMM ------------------
// 3-stage cp.async ring, ONE barrier per chunk.
#define PAD      40
#define MAT_B    (128 * PAD * 2)
#define STAGE_B  (2 * MAT_B)
#define NKCH     (KD_ / 32)

__global__ __launch_bounds__(256, 2) void proj_all_kernel(
    const float* __restrict__ bq, const float* __restrict__ bk,
    const float* __restrict__ bv)
{
    extern __shared__ char psm[];

    const int tid  = threadIdx.x;
    const int wid  = tid >> 5;
    const int lane = tid & 31;
    const int wm   = wid >> 2;
    const int wn   = wid & 3;
    const int bm   = blockIdx.y * 128;
    const int bn   = blockIdx.x * 128;
    const int z    = blockIdx.z;

    const __half* xhi  = g_xhi  + (size_t)z * M_ * KD_;
    const __half* whiT = g_wThi + (size_t)z * N_ * KD_;
    const float* bias = (z == 0) ? bq : (z == 1) ? bk : bv;
    const float scale = (z == 0) ? 0.125f : 1.0f;

    float acc[4][4][4];
    #pragma unroll
    for (int i = 0; i < 4; i++)
        #pragma unroll
        for (int j = 0; j < 4; j++)
            #pragma unroll
            for (int r = 0; r < 4; r++) acc[i][j][r] = 0.f;

    auto load_stage = [&](int c, int s) {
        const int k0 = c * 32;
        char* st = psm + s * STAGE_B;
        #pragma unroll
        for (int t = 0; t < 4; t++) {
            int idx = tid + t * 256;
            int mat = idx >> 9;               // 0:aHi 1:bHi
            int rr  = (idx >> 2) & 127;
            int u   = idx & 3;
            const __half* src = (mat == 0) ? xhi : whiT;
            size_t off = (mat == 0)
                ? (size_t)(bm + rr) * KD_ + k0 + u * 8
                : (size_t)(bn + rr) * KD_ + k0 + u * 8;
            cp16(st + mat * MAT_B + rr * (PAD * 2) + u * 16, src + off);
        }
        CP_COMMIT();
    };

    const int fr   = lane >> 2;
    const int fc   = (lane & 3) * 2;
    const int lrow = lane & 7;
    const int lm   = lane >> 3;
    const uint32_t psm_u = smem_u32(psm);

    auto compute = [&](int s) {
        const uint32_t aHi = psm_u + s * STAGE_B;
        const uint32_t bHi = aHi + MAT_B;
        #pragma unroll
        for (int ks = 0; ks < 2; ks++) {
            const int kc = ks * 16;
            const uint32_t aoff = (uint32_t)(((lm & 1) * 8 + lrow) * (PAD * 2)
                                             + (kc + (lm >> 1) * 8) * 2);
            const uint32_t boff = (uint32_t)(((lm >> 1) * 8 + lrow) * (PAD * 2)
                                             + (kc + (lm & 1) * 8) * 2);
            uint32_t af[4][4], bh[8];
            #pragma unroll
            for (int i = 0; i < 4; i++) {
                uint32_t ra = (uint32_t)((wm * 64 + i * 16) * (PAD * 2));
                ldsm4(af[i], aHi + ra + aoff);
            }
            #pragma unroll
            for (int jb = 0; jb < 2; jb++) {
                uint32_t rb = (uint32_t)((wn * 32 + jb * 16) * (PAD * 2));
                ldsm4(&bh[jb * 4], bHi + rb + boff);
            }
            #pragma unroll
            for (int i = 0; i < 4; i++)
                #pragma unroll
                for (int j = 0; j < 4; j++)
                    mma_f16(acc[i][j], af[i][0], af[i][1], af[i][2], af[i][3],
                            bh[j * 2], bh[j * 2 + 1]);
        }
    };

    load_stage(0, 0);
    load_stage(1, 1);
    for (int c = 0; c < NKCH; c++) {
        if (c + 1 < NKCH) { CP_WAIT1(); } else { CP_WAIT0(); }
        __syncthreads();
        compute(c % 3);
        if (c + 2 < NKCH) load_stage(c + 2, (c + 2) % 3);
    }

    // epilogue: bias+scale, round to fp16, write (V transposed when z==2)
    #pragma unroll
    for (int i = 0; i < 4; i++) {
        #pragma unroll
        for (int rr = 0; rr < 2; rr++) {
            int m = bm + wm * 64 + i * 16 + fr + rr * 8;
            int b = m >> 11;
            int sdx = m & (S_ - 1);
            #pragma unroll
            for (int j = 0; j < 4; j++) {
                int n0 = bn + wn * 32 + j * 8 + fc;
                int h  = n0 >> 6;
                int d  = n0 & 63;
                float x0 = (acc[i][j][rr * 2 + 0] + bias[n0 + 0]) * scale;
                float x1 = (acc[i][j][rr * 2 + 1] + bias[n0 + 1]) * scale;
                __half h0 = __float2half(x0);
                __half h1 = __float2half(x1);
                if (z == 0) {
                    size_t o = (((size_t)(b * H_ + h) * S_) + sdx) * DK_ + d;
                    __half2 ph; ph.x = h0; ph.y = h1;
                    *(__half2*)&g_qh[o] = ph;
                } else if (z == 1) {
                    size_t o = (((size_t)(b * H_ + h) * S_) + sdx) * DK_ + d;
                    __half2 ph; ph.x = h0; ph.y = h1;
                    *(__half2*)&g_kh[o] = ph;
                } else {
                    size_t o = ((size_t)(b * H_ + h) * DK_ + d) * S_ + sdx;
                    g_vth[o] = h0; g_vth[o + S_] = h1;
                }
            }
        }
    }
}

// ---------------- tensor-core attention ------------------------------------
// BR=128, 4 warps x 32 q-rows (128 threads), 3-stage ring, 1 barrier/chunk.
#define BR   128
#define ATH  128
#define KC   64
#define NCHA (S_ / KC)     // 32
#define QSTR 144           // bytes/row (72 halves)
#define KMAT (64 * QSTR)   // 9216
#define STG  (2 * KMAT + 256)      // 18688 (kh + vh + mask)
#define OFFK (BR * QSTR)           // 18432 (after qh)

__global__ __launch_bounds__(ATH, 2) void attn_mma_kernel(
    const float* __restrict__ maskg, float* __restrict__ out)
{
    extern __shared__ char smc[];

    const int tid  = threadIdx.x;
    const int wid  = tid >> 5;           // 0..3
    const int lane = tid & 31;
    const int fr   = lane >> 2;
    const int fc   = (lane & 3) * 2;
    const int lrow = lane & 7;
    const int lm   = lane >> 3;
    const int bh   = blockIdx.y;
    const int b    = bh >> 4;
    const int h    = bh & 15;
    const int bm   = blockIdx.x * BR;
    const int wq0  = wid * 32;           // 32 q-rows per warp

    const __half* qh_g = g_qh + ((size_t)bh * S_ + bm) * DK_;

    // Q load (joins chunk 0's commit group): 1024 16B units over 128 threads
    #pragma unroll
    for (int t = 0; t < 8; t++) {
        int idx = tid + t * ATH;
        int r = idx >> 3, u = idx & 7;
        cp16(smc + r * QSTR + u * 16, qh_g + r * DK_ + u * 8);
    }

    auto load_chunk = [&](int c, int s) {
        const int k0 = c * KC;
        char* st = smc + OFFK + s * STG;
        #pragma unroll
        for (int t = 0; t < 4; t++) {
            int idx = tid + t * ATH;      // 0..511 : 64 rows x 8 units
            int r = idx >> 3, u = idx & 7;
            cp16(st + r * QSTR + u * 16,
                 g_kh + ((size_t)bh * S_ + k0 + r) * DK_ + u * 8);
            cp16(st + KMAT + r * QSTR + u * 16,
                 g_vth + ((size_t)bh * DK_ + r) * S_ + k0 + u * 8);
        }
        if (tid < 16) cp16(st + 2 * KMAT + tid * 16, maskg + (size_t)b * S_ + k0 + tid * 4);
        CP_COMMIT();
    };

    load_chunk(0, 0);
    load_chunk(1, 1);

    uint32_t qf[4][8];                   // [kt][mt*4 + j]
    float accO[2][8][4];
    #pragma unroll
    for (int mt = 0; mt < 2; mt++)
        #pragma unroll
        for (int n = 0; n < 8; n++)
            #pragma unroll
            for (int r = 0; r < 4; r++) accO[mt][n][r] = 0.f;
    float den[2][2] = {{0.f, 0.f}, {0.f, 0.f}};

    const uint32_t smc_u = smem_u32(smc);
    const uint32_t lboff = (uint32_t)(((lm >> 1) * 8 + lrow) * QSTR + (lm & 1) * 16);

    for (int c = 0; c < NCHA; c++) {
        const int s = c % 3;
        if (c + 1 < NCHA) { CP_WAIT1(); } else { CP_WAIT0(); }
        __syncthreads();

        if (c == 0) {
            const char* qhB = smc;
            #pragma unroll
            for (int kt = 0; kt < 4; kt++) {
                int cb = (kt * 16 + fc) * 2;
                #pragma unroll
                for (int mt = 0; mt < 2; mt++) {
                    int r0 = wq0 + mt * 16 + fr;
                    qf[kt][mt*4+0] = *(const uint32_t*)(qhB + r0 * QSTR + cb);
                    qf[kt][mt*4+1] = *(const uint32_t*)(qhB + (r0 + 8) * QSTR + cb);
                    qf[kt][mt*4+2] = *(const uint32_t*)(qhB + r0 * QSTR + cb + 16);
                    qf[kt][mt*4+3] = *(const uint32_t*)(qhB + (r0 + 8) * QSTR + cb + 16);
                }
            }
        }

        const uint32_t khu = smc_u + OFFK + (uint32_t)(s * STG);
        const uint32_t vhu = khu + KMAT;
        const float* mk = (const float*)(smc + OFFK + s * STG + 2 * KMAT);

        // ---- scores (fp16, 1 term, 2 m-tiles share each B fragment)
        float accs[2][8][4];
        #pragma unroll
        for (int mt = 0; mt < 2; mt++)
            #pragma unroll
            for (int n = 0; n < 8; n++)
                #pragma unroll
                for (int r = 0; r < 4; r++) accs[mt][n][r] = 0.f;

        #pragma unroll
        for (int kt = 0; kt < 4; kt++) {
            #pragma unroll
            for (int np = 0; np < 4; np++) {
                uint32_t off = (uint32_t)(np * 16 * QSTR + kt * 32) + lboff;
                uint32_t bh4[4];
                ldsm4(bh4, khu + off);
                #pragma unroll
                for (int mt = 0; mt < 2; mt++) {
                    mma_f16(accs[mt][2*np],   qf[kt][mt*4+0], qf[kt][mt*4+1],
                            qf[kt][mt*4+2], qf[kt][mt*4+3], bh4[0], bh4[1]);
                    mma_f16(accs[mt][2*np+1], qf[kt][mt*4+0], qf[kt][mt*4+1],
                            qf[kt][mt*4+2], qf[kt][mt*4+3], bh4[2], bh4[3]);
                }
            }
        }

        // ---- P = exp(s) * mask; fp16 pack; denom (fp32, pre-rounding)
        uint32_t phf[2][4][4];
        #pragma unroll
        for (int mt = 0; mt < 2; mt++) {
            #pragma unroll
            for (int nt = 0; nt < 8; nt++) {
                float m0 = mk[nt * 8 + fc];
                float m1 = mk[nt * 8 + fc + 1];
                #pragma unroll
                for (int rr = 0; rr < 2; rr++) {
                    float p0 = __expf(accs[mt][nt][rr * 2 + 0]) * m0;
                    float p1 = __expf(accs[mt][nt][rr * 2 + 1]) * m1;
                    den[mt][rr] += p0 + p1;
                    phf[mt][nt >> 1][(nt & 1) * 2 + rr] = pack_f16x2(p0, p1);
                }
            }
        }

        // ---- O += P @ V (fp16, 1 term)
        #pragma unroll
        for (int kt = 0; kt < 4; kt++) {
            #pragma unroll
            for (int np = 0; np < 4; np++) {
                uint32_t off = (uint32_t)(np * 16 * QSTR + kt * 32) + lboff;
                uint32_t vh4[4];
                ldsm4(vh4, vhu + off);
                #pragma unroll
                for (int mt = 0; mt < 2; mt++) {
                    mma_f16(accO[mt][2*np],   phf[mt][kt][0], phf[mt][kt][1],
                            phf[mt][kt][2], phf[mt][kt][3], vh4[0], vh4[1]);
                    mma_f16(accO[mt][2*np+1], phf[mt][kt][0], phf[mt][kt][1],
                            phf[mt][kt][2], phf[mt][kt][3], vh4[2], vh4[3]);
                }
            }
        }

        if (c + 2 < NCHA) load_chunk(c + 2, (c + 2) % 3);
    }

    #pragma unroll
    for (int mt = 0; mt < 2; mt++)
        #pragma unroll
        for (int rr = 0; rr < 2; rr++) {
            float d = den[mt][rr];
            d += __shfl_xor_sync(0xffffffffu, d, 1);
            d += __shfl_xor_sync(0xffffffffu, d, 2);
            den[mt][rr] = 1.f / (d + 1e-8f);
        }

    #pragma unroll
    for (int mt = 0; mt < 2; mt++) {
        int q = bm + wq0 + mt * 16 + fr;
        #pragma unroll
        for (int nt = 0; nt < 8; nt++) {
            int col = h * DK_ + nt * 8 + fc;
            float2 o0; o0.x = accO[mt][nt][0] * den[mt][0]; o0.y = accO[mt][nt][1] * den[mt][0];
            float2 o1; o1.x = accO[mt][nt][2] * den[mt][1]; o1.y = accO[mt][nt][3] * den[mt][1];
            *(float2*)&out[((size_t)(b * S_ + q)) * N_ + col] = o0;
            *(float2*)&out[((size_t)(b * S_ + q + 8)) * N_ + col] = o1;
        }
    }
}

// ---------------------------------------------------------------------------
extern "C" void kernel_launch(void* const* d_in, const int* in_sizes, int n_in,
                              void* d_out, int out_size)
{
    const float* Q    = (const float*)d_in[0];
    const float* Kin  = (const float*)d_in[1];
    const float* Vin  = (const float*)d_in[2];
    const float* mask = (const float*)d_in[3];
    const float* Wq   = (const float*)d_in[4];
    const float* bq   = (const float*)d_in[5];
    const float* Wk   = (const float*)d_in[6];
    const float* bk   = (const float*)d_in[7];
    const float* Wv   = (const float*)d_in[8];
    const float* bv   = (const float*)d_in[9];
    float* out = (float*)d_out;

    __half *xhi, *whiT;
    cudaGetSymbolAddress((void**)&xhi,  g_xhi);
    cudaGetSymbolAddress((void**)&whiT, g_wThi);

    const int psmem = 3 * STAGE_B;   // 61440
    cudaFuncSetAttribute(proj_all_kernel,
                         cudaFuncAttributeMaxDynamicSharedMemorySize, psmem);

    const int n4 = (M_ * KD_) / 4;
    split_all_kernel<<<dim3((n4 + 255) / 256, 3), 256>>>(
        (const float4*)Q, (const float4*)Kin, (const float4*)Vin,
        (uint2*)xhi, n4);
    splitT_all_kernel<<<dim3(N_ / 32, KD_ / 32, 3), dim3(32, 8)>>>(
        Wq, Wk, Wv, whiT);
    proj_all_kernel<<<dim3(N_ / 128, M_ / 128, 3), 256, psmem>>>(bq, bk, bv);

    const int asmem = OFFK + 3 * STG;   // 18432 + 56064 = 74496
    cudaFuncSetAttribute(attn_mma_kernel,
                         cudaFuncAttributeMaxDynamicSharedMemorySize, asmem);
    attn_mma_kernel<<<dim3(S_ / BR, B_ * H_), ATH, asmem>>>(mask, out);
}